// round 11
// baseline (speedup 1.0000x reference)
#include <cuda_runtime.h>
#include <cuda_bf16.h>
#include <math.h>
#include <stdint.h>

#define BN 8192
#define CN 128
#define NL 8
#define BC (BN*CN)
#define SLICE (BC*8)
#define AMU_SIZE (BN*32)
#define EPSF 1e-6f
#define KL 160   // lift K padded (132 -> 160)
#define SAL 88   // lift SMEM row stride (bf16): conflict-free
#define SA 72    // gemm SMEM row stride (bf16): 36 words == 4 mod 32 -> conflict-free

// ------------------------- device scratch -------------------------
__device__ __nv_bfloat16 g_feats_hi[BN*KL];
__device__ __nv_bfloat16 g_feats_lo[BN*KL];
__device__ __nv_bfloat16 g_LW_hi[1024*KL];      // liftW transposed [n][k]
__device__ __nv_bfloat16 g_LW_lo[1024*KL];
__device__ __nv_bfloat16 g_Wb_hi[NL*8*CN*CN];   // [l][kb][o][i]
__device__ __nv_bfloat16 g_Wb_lo[NL*8*CN*CN];
__device__ float g_rotM[NL*64*CN];              // transposed rotor matrices [l][jk][c]
__device__ float g_h[BC*8];                     // lift output interleaved
__device__ float g_res[BC*8];                   // layer-0 residual
__device__ __nv_bfloat16 g_act_hi[8*BC];        // blade-planar activations (hi)
__device__ __nv_bfloat16 g_act_lo[8*BC];        // (lo)
__device__ float g_gout[8*BC];                  // blade-planar gemm output

__device__ const int c_blades[8] = {0,1,2,4,3,5,6,7};

__device__ __forceinline__ int cl_sign(int a, int b) {
    int s = 0; int aa = a >> 1;
    while (aa) { s += __popc(aa & b); aa >>= 1; }
    return (s & 1) ? -1 : 1;
}

__device__ __forceinline__ void mma16816(float* c, const uint32_t* a, const uint32_t* b) {
    asm volatile("mma.sync.aligned.m16n8k16.row.col.f32.bf16.bf16.f32 "
        "{%0,%1,%2,%3}, {%4,%5,%6,%7}, {%8,%9}, {%0,%1,%2,%3};"
        : "+f"(c[0]), "+f"(c[1]), "+f"(c[2]), "+f"(c[3])
        : "r"(a[0]), "r"(a[1]), "r"(a[2]), "r"(a[3]), "r"(b[0]), "r"(b[1]));
}

// ------------------------- rotor matrix precompute -------------------------
__global__ void rotor_pre(const float* __restrict__ theta) {
    int n = blockIdx.x * blockDim.x + threadIdx.x;
    if (n >= NL * CN) return;
    int l = n / CN, c = n % CN;
    const float* t = theta + n * 3;
    float ang = sqrtf(t[0]*t[0] + t[1]*t[1] + t[2]*t[2] + EPSF);
    float R[8] = {0,0,0,0,0,0,0,0};
    R[0] = cosf(ang);
    float s = sinf(ang) / ang;
    R[4] = s * t[0]; R[5] = s * t[1]; R[6] = s * t[2];
    float Rr[8];
    #pragma unroll
    for (int i = 0; i < 8; i++) Rr[i] = (i >= 4) ? -R[i] : R[i];
    float M[64];
    #pragma unroll
    for (int i = 0; i < 64; i++) M[i] = 0.0f;
    const int iv[4] = {0, 4, 5, 6};
    for (int ii = 0; ii < 4; ii++) {
        int i = iv[ii]; float Ri = R[i]; int a = c_blades[i];
        for (int j = 0; j < 8; j++) {
            int bb = c_blades[j];
            int m_mask = a ^ bb;
            float tj = Ri * (float)cl_sign(a, bb);
            for (int pp = 0; pp < 4; pp++) {
                int p = iv[pp]; int pm = c_blades[p];
                int k_mask = m_mask ^ pm;
                float s2 = (float)cl_sign(m_mask, pm);
                int k = c_blades[k_mask];
                M[j*8 + k] += tj * Rr[p] * s2;
            }
        }
    }
    float* out = g_rotM + (size_t)l*64*CN + c;
    #pragma unroll
    for (int i = 0; i < 64; i++) out[(size_t)i*CN] = M[i];
}

// ------------------------- weight repack to bf16 split [l][kb][o][i] -------------------------
__global__ void repack(const float* __restrict__ linW) {
    int n = blockIdx.x * 256 + threadIdx.x;
    if (n >= NL*8*CN*CN) return;
    int i = n & 127;
    int o = (n >> 7) & 127;
    int kb = (n >> 14) & 7;
    int l = n >> 17;
    float w = linW[(size_t)(((l*128 + o)*128 + i) * 8) + kb];
    __nv_bfloat16 hi = __float2bfloat16(w);
    g_Wb_hi[n] = hi;
    g_Wb_lo[n] = __float2bfloat16(w - __bfloat162float(hi));
}

// ------------------------- lift weight repack -------------------------
__global__ void repack_lift(const float* __restrict__ liftW) {
    int n = blockIdx.x * 256 + threadIdx.x;
    if (n >= 1024*KL) return;
    int k = n % KL;
    int o = n / KL;
    float w = (k < 132) ? liftW[(size_t)k*1024 + o] : 0.0f;
    __nv_bfloat16 hi = __float2bfloat16(w);
    g_LW_hi[n] = hi;
    g_LW_lo[n] = __float2bfloat16(w - __bfloat162float(hi));
}

// ------------------------- features (bf16 hi/lo planes) -------------------------
__global__ void feats_kernel(const float* __restrict__ coords, const float* __restrict__ freq) {
    int gid = blockIdx.x * 256 + threadIdx.x;
    int row = gid >> 5, lane = gid & 31;
    if (row >= BN) return;
    float c0 = coords[row*4+0], c1 = coords[row*4+1];
    float c2 = coords[row*4+2], c3 = coords[row*4+3];
    __nv_bfloat16* oh = g_feats_hi + (size_t)row * KL;
    __nv_bfloat16* ol = g_feats_lo + (size_t)row * KL;
    if (lane < 4) {
        float v = coords[row*4 + lane];
        __nv_bfloat16 hi = __float2bfloat16(v);
        oh[lane] = hi; ol[lane] = __float2bfloat16(v - __bfloat162float(hi));
    }
    #pragma unroll
    for (int f = lane; f < 64; f += 32) {
        float p = c0*freq[f] + c1*freq[64+f] + c2*freq[128+f] + c3*freq[192+f];
        float sv = sinf(p), cv = cosf(p);
        __nv_bfloat16 sh = __float2bfloat16(sv);
        __nv_bfloat16 ch = __float2bfloat16(cv);
        oh[4 + f]  = sh; ol[4 + f]  = __float2bfloat16(sv - __bfloat162float(sh));
        oh[68 + f] = ch; ol[68 + f] = __float2bfloat16(cv - __bfloat162float(ch));
    }
    if (lane < 28) {
        oh[132 + lane] = __float2bfloat16(0.0f);
        ol[132 + lane] = __float2bfloat16(0.0f);
    }
}

// ------------------------- lift GEMM via mma -------------------------
__global__ void __launch_bounds__(256, 2) lift_mma(const float* __restrict__ liftb) {
    extern __shared__ __nv_bfloat16 sm[];
    __nv_bfloat16* sAhi = sm;
    __nv_bfloat16* sAlo = sm + 128*SAL;
    __nv_bfloat16* sBhi = sm + 2*128*SAL;
    __nv_bfloat16* sBlo = sm + 3*128*SAL;

    int tid = threadIdx.x;
    int wid = tid >> 5, lane = tid & 31;
    int group = lane >> 2, tig = lane & 3;
    int m_warp = (wid & 3) * 32;
    int n_warp = (wid >> 2) * 64;

    int nb = blockIdx.x << 7;
    int mb = blockIdx.y << 7;

    const __nv_bfloat16* Ahi = g_feats_hi + (size_t)mb*KL;
    const __nv_bfloat16* Alo = g_feats_lo + (size_t)mb*KL;
    const __nv_bfloat16* Bhi = g_LW_hi + (size_t)nb*KL;
    const __nv_bfloat16* Blo = g_LW_lo + (size_t)nb*KL;

    float acc[2][8][4];
    #pragma unroll
    for (int f = 0; f < 2; f++)
        #pragma unroll
        for (int g = 0; g < 8; g++)
            #pragma unroll
            for (int q = 0; q < 4; q++) acc[f][g][q] = 0.0f;

    #pragma unroll
    for (int chunk = 0; chunk < 2; chunk++) {
        int kc = chunk * 80;
        #pragma unroll
        for (int i = 0; i < 5; i++) {
            int idx = tid + 256*i;
            int row = idx / 10, ch = idx % 10;
            size_t src = (size_t)row*KL + kc + ch*8;
            int dst = row*SAL + ch*8;
            *(uint4*)&sAhi[dst] = *(const uint4*)&Ahi[src];
            *(uint4*)&sAlo[dst] = *(const uint4*)&Alo[src];
            *(uint4*)&sBhi[dst] = *(const uint4*)&Bhi[src];
            *(uint4*)&sBlo[dst] = *(const uint4*)&Blo[src];
        }
        __syncthreads();

        #pragma unroll
        for (int ks = 0; ks < 5; ks++) {
            int k0 = ks * 16;
            uint32_t ahi[2][4], alo[2][4];
            #pragma unroll
            for (int f = 0; f < 2; f++) {
                int r0 = (m_warp + f*16 + group) * SAL + k0 + tig*2;
                int r8 = r0 + 8*SAL;
                ahi[f][0] = *(const uint32_t*)&sAhi[r0];
                ahi[f][1] = *(const uint32_t*)&sAhi[r8];
                ahi[f][2] = *(const uint32_t*)&sAhi[r0 + 8];
                ahi[f][3] = *(const uint32_t*)&sAhi[r8 + 8];
                alo[f][0] = *(const uint32_t*)&sAlo[r0];
                alo[f][1] = *(const uint32_t*)&sAlo[r8];
                alo[f][2] = *(const uint32_t*)&sAlo[r0 + 8];
                alo[f][3] = *(const uint32_t*)&sAlo[r8 + 8];
            }
            #pragma unroll
            for (int g = 0; g < 8; g++) {
                int nrow = (n_warp + g*8 + group) * SAL + k0 + tig*2;
                uint32_t bhi[2], blo[2];
                bhi[0] = *(const uint32_t*)&sBhi[nrow];
                bhi[1] = *(const uint32_t*)&sBhi[nrow + 8];
                blo[0] = *(const uint32_t*)&sBlo[nrow];
                blo[1] = *(const uint32_t*)&sBlo[nrow + 8];
                #pragma unroll
                for (int f = 0; f < 2; f++) {
                    mma16816(acc[f][g], ahi[f], bhi);
                    mma16816(acc[f][g], ahi[f], blo);
                    mma16816(acc[f][g], alo[f], bhi);
                }
            }
        }
        __syncthreads();
    }

    #pragma unroll
    for (int f = 0; f < 2; f++) {
        #pragma unroll
        for (int g = 0; g < 8; g++) {
            int row = mb + m_warp + f*16 + group;
            int col = nb + n_warp + g*8 + tig*2;
            float b0 = liftb[col], b1 = liftb[col+1];
            float* p = g_h + (size_t)row*1024 + col;
            *(float2*)p = make_float2(acc[f][g][0] + b0, acc[f][g][1] + b1);
            *(float2*)(p + 8*1024) = make_float2(acc[f][g][2] + b0, acc[f][g][3] + b1);
        }
    }
}

// ------------------------- mma.sync blade GEMM (3 CTAs/SM, single-buffer k64) -------------------------
__global__ void __launch_bounds__(256, 3) gemm_mma(int l) {
    extern __shared__ __nv_bfloat16 sm[];
    __nv_bfloat16* sAhi = sm;
    __nv_bfloat16* sAlo = sm + 128*SA;
    __nv_bfloat16* sBhi = sm + 2*128*SA;
    __nv_bfloat16* sBlo = sm + 3*128*SA;

    int tid = threadIdx.x;
    int wid = tid >> 5, lane = tid & 31;
    int group = lane >> 2, tig = lane & 3;
    int m_warp = (wid & 3) * 32;
    int n_warp = (wid >> 2) * 64;

    int kb = blockIdx.y;              // blade slow -> consecutive CTAs share weights
    int mb = blockIdx.x << 7;

    const __nv_bfloat16* Ahi = g_act_hi + (size_t)kb*BC + (size_t)mb*128;
    const __nv_bfloat16* Alo = g_act_lo + (size_t)kb*BC + (size_t)mb*128;
    const __nv_bfloat16* Bhi = g_Wb_hi + (size_t)(l*8 + kb)*CN*CN;
    const __nv_bfloat16* Blo = g_Wb_lo + (size_t)(l*8 + kb)*CN*CN;

    float acc[2][8][4];
    #pragma unroll
    for (int f = 0; f < 2; f++)
        #pragma unroll
        for (int g = 0; g < 8; g++)
            #pragma unroll
            for (int q = 0; q < 4; q++) acc[f][g][q] = 0.0f;

    #pragma unroll
    for (int chunk = 0; chunk < 2; chunk++) {
        int kc = chunk * 64;
        #pragma unroll
        for (int i = 0; i < 4; i++) {
            int idx = tid + 256*i;
            int row = idx >> 3, ch = idx & 7;
            size_t src = (size_t)row*128 + kc + ch*8;
            int dst = row*SA + ch*8;
            *(uint4*)&sAhi[dst] = *(const uint4*)&Ahi[src];
            *(uint4*)&sAlo[dst] = *(const uint4*)&Alo[src];
            *(uint4*)&sBhi[dst] = *(const uint4*)&Bhi[src];
            *(uint4*)&sBlo[dst] = *(const uint4*)&Blo[src];
        }
        __syncthreads();

        #pragma unroll
        for (int ks = 0; ks < 4; ks++) {
            int k0 = ks * 16;
            uint32_t ahi[2][4], alo[2][4];
            #pragma unroll
            for (int f = 0; f < 2; f++) {
                int r0 = (m_warp + f*16 + group) * SA + k0 + tig*2;
                int r8 = r0 + 8*SA;
                ahi[f][0] = *(const uint32_t*)&sAhi[r0];
                ahi[f][1] = *(const uint32_t*)&sAhi[r8];
                ahi[f][2] = *(const uint32_t*)&sAhi[r0 + 8];
                ahi[f][3] = *(const uint32_t*)&sAhi[r8 + 8];
                alo[f][0] = *(const uint32_t*)&sAlo[r0];
                alo[f][1] = *(const uint32_t*)&sAlo[r8];
                alo[f][2] = *(const uint32_t*)&sAlo[r0 + 8];
                alo[f][3] = *(const uint32_t*)&sAlo[r8 + 8];
            }
            #pragma unroll
            for (int g = 0; g < 8; g++) {
                int nrow = (n_warp + g*8 + group) * SA + k0 + tig*2;
                uint32_t bhi[2], blo[2];
                bhi[0] = *(const uint32_t*)&sBhi[nrow];
                bhi[1] = *(const uint32_t*)&sBhi[nrow + 8];
                blo[0] = *(const uint32_t*)&sBlo[nrow];
                blo[1] = *(const uint32_t*)&sBlo[nrow + 8];
                #pragma unroll
                for (int f = 0; f < 2; f++) {
                    mma16816(acc[f][g], ahi[f], bhi);
                    mma16816(acc[f][g], ahi[f], blo);
                    mma16816(acc[f][g], alo[f], bhi);
                }
            }
        }
        __syncthreads();
    }

    float* gbase = g_gout + (size_t)kb*BC;
    #pragma unroll
    for (int f = 0; f < 2; f++) {
        #pragma unroll
        for (int g = 0; g < 8; g++) {
            int row = mb + m_warp + f*16 + group;
            int col = n_warp + g*8 + tig*2;
            float* p = gbase + (size_t)row*128 + col;
            *(float2*)p = make_float2(acc[f][g][0], acc[f][g][1]);
            *(float2*)(p + 8*128) = make_float2(acc[f][g][2], acc[f][g][3]);
        }
    }
}

// ------------------------- pointwise helpers -------------------------
__device__ __forceinline__ void grade_inv(const float* x, float* inv, float (*sred)[4], int c) {
    float v[4];
    v[0] = x[0]*x[0];
    v[1] = x[1]*x[1] + x[2]*x[2] + x[3]*x[3];
    v[2] = x[4]*x[4] + x[5]*x[5] + x[6]*x[6];
    v[3] = x[7]*x[7];
    #pragma unroll
    for (int g = 0; g < 4; g++) {
        float t = v[g];
        t += __shfl_xor_sync(0xffffffffu, t, 16);
        t += __shfl_xor_sync(0xffffffffu, t, 8);
        t += __shfl_xor_sync(0xffffffffu, t, 4);
        t += __shfl_xor_sync(0xffffffffu, t, 2);
        t += __shfl_xor_sync(0xffffffffu, t, 1);
        if ((c & 31) == 0) sred[g][c >> 5] = t;
    }
    __syncthreads();
    #pragma unroll
    for (int g = 0; g < 4; g++)
        inv[g] = rsqrtf((sred[g][0]+sred[g][1]+sred[g][2]+sred[g][3]) * (1.0f/128.0f) + EPSF);
    __syncthreads();
}

__device__ __forceinline__ void ln_apply(float* x, const float* gamma, const float* inv, int c) {
    float f0 = gamma[c*4+0] * inv[0];
    float f1 = gamma[c*4+1] * inv[1];
    float f2 = gamma[c*4+2] * inv[2];
    float f3 = gamma[c*4+3] * inv[3];
    x[0] *= f0;
    x[1] *= f1; x[2] *= f1; x[3] *= f1;
    x[4] *= f2; x[5] *= f2; x[6] *= f2;
    x[7] *= f3;
}

__device__ __forceinline__ void rot_gelu_store(const float* x, const float* __restrict__ Mt,
                                               float alpha, int b, int c) {
    float y[8] = {0,0,0,0,0,0,0,0};
    #pragma unroll
    for (int j = 0; j < 8; j++) {
        float xj = x[j];
        #pragma unroll
        for (int k = 0; k < 8; k++)
            y[k] = fmaf(xj, __ldg(Mt + (size_t)(j*8+k)*CN + c), y[k]);
    }
    float nn = EPSF;
    #pragma unroll
    for (int k = 0; k < 8; k++) nn = fmaf(y[k], y[k], nn);
    float gate = 0.5f * (1.0f + erff(alpha * sqrtf(nn) * 0.70710678118654752f));
    #pragma unroll
    for (int k = 0; k < 8; k++) {
        float v = y[k] * gate;
        __nv_bfloat16 hi = __float2bfloat16(v);
        size_t idx = (size_t)k*BC + b*128 + c;
        g_act_hi[idx] = hi;
        g_act_lo[idx] = __float2bfloat16(v - __bfloat162float(hi));
    }
}

// ------------------------- input norm + layer-0 prologue -------------------------
__global__ void __launch_bounds__(256) ln_in_kernel(const float* __restrict__ in_gamma,
                                                    const float* __restrict__ ng0,
                                                    const float* __restrict__ alpha0) {
    __shared__ float sred[2][4][4];
    int row = threadIdx.x >> 7;
    int c = threadIdx.x & 127;
    int b = blockIdx.x * 2 + row;
    float x[8];
    const float* p = g_h + (size_t)(b*128 + c) * 8;
    *(float4*)x     = *(const float4*)p;
    *(float4*)(x+4) = *(const float4*)(p+4);

    float inv[4];
    grade_inv(x, inv, sred[row], c);
    ln_apply(x, in_gamma, inv, c);

    float* pr = g_res + (size_t)(b*128 + c) * 8;
    *(float4*)pr     = *(const float4*)x;
    *(float4*)(pr+4) = *(const float4*)(x+4);

    grade_inv(x, inv, sred[row], c);
    ln_apply(x, ng0, inv, c);
    rot_gelu_store(x, g_rotM, alpha0[c], b, c);
}

// ------------------------- inter-layer pointwise (final layer fuses projection) ------------
__global__ void __launch_bounds__(256) ip_kernel(const float* __restrict__ Mt_next,
                                                 const float* __restrict__ linb,
                                                 const float* __restrict__ resIn,
                                                 float* __restrict__ outI,
                                                 const float* __restrict__ gamma_next,
                                                 const float* __restrict__ alpha_next,
                                                 const float* __restrict__ projW,
                                                 const float* __restrict__ projb,
                                                 float* __restrict__ outA,
                                                 int final_ln) {
    __shared__ float sred[2][4][4];
    __shared__ float sproj[8][12];
    int row = threadIdx.x >> 7;
    int c = threadIdx.x & 127;
    int b = blockIdx.x * 2 + row;
    float x[8];
    #pragma unroll
    for (int k = 0; k < 8; k++)
        x[k] = g_gout[(size_t)k*BC + b*128 + c] + linb[c*8 + k];

    const float* pr = resIn + (size_t)(b*128 + c) * 8;
    float r[8];
    *(float4*)r     = *(const float4*)pr;
    *(float4*)(r+4) = *(const float4*)(pr+4);
    #pragma unroll
    for (int k = 0; k < 8; k++) x[k] += r[k];

    float* po = outI + (size_t)(b*128 + c) * 8;
    *(float4*)po     = *(const float4*)x;
    *(float4*)(po+4) = *(const float4*)(x+4);

    float inv[4];
    grade_inv(x, inv, sred[row], c);
    ln_apply(x, gamma_next, inv, c);

    if (!final_ln) {
        rot_gelu_store(x, Mt_next, alpha_next[c], b, c);
    } else {
        float p[12];
        #pragma unroll
        for (int o = 0; o < 4; o++)
            #pragma unroll
            for (int kk = 0; kk < 3; kk++)
                p[o*3+kk] = x[4+kk] * __ldg(projW + (size_t)(o*128 + c)*8 + 4 + kk);
        #pragma unroll
        for (int q = 0; q < 12; q++) {
            float t = p[q];
            t += __shfl_xor_sync(0xffffffffu, t, 16);
            t += __shfl_xor_sync(0xffffffffu, t, 8);
            t += __shfl_xor_sync(0xffffffffu, t, 4);
            t += __shfl_xor_sync(0xffffffffu, t, 2);
            t += __shfl_xor_sync(0xffffffffu, t, 1);
            p[q] = t;
        }
        int wp = threadIdx.x >> 5;
        if ((threadIdx.x & 31) == 0) {
            #pragma unroll
            for (int q = 0; q < 12; q++) sproj[wp][q] = p[q];
        }
        __syncthreads();
        int tid = threadIdx.x;
        if (tid < 64) {
            int rr = tid >> 5, j = tid & 31;
            int k = j & 7;
            int bb = blockIdx.x * 2 + rr;
            if (k < 4 || k > 6) outA[(size_t)bb*32 + j] = 0.0f;
        }
        if (tid < 24) {
            int rr = tid / 12, q = tid % 12;
            int o = q / 3, k = 4 + q % 3;
            int bb = blockIdx.x * 2 + rr;
            float s = sproj[rr*4+0][q] + sproj[rr*4+1][q] + sproj[rr*4+2][q] + sproj[rr*4+3][q];
            outA[(size_t)bb*32 + o*8 + k] = s + projb[o*8 + k];
        }
    }
}

// ------------------------- launch -------------------------
extern "C" void kernel_launch(void* const* d_in, const int* in_sizes, int n_in,
                              void* d_out, int out_size) {
    const float* coords     = (const float*)d_in[0];
    const float* freq       = (const float*)d_in[1];
    const float* liftW      = (const float*)d_in[2];
    const float* liftb      = (const float*)d_in[3];
    const float* in_gamma   = (const float*)d_in[4];
    const float* norm_gamma = (const float*)d_in[5];
    const float* rotor_th   = (const float*)d_in[6];
    const float* act_alpha  = (const float*)d_in[7];
    const float* linW       = (const float*)d_in[8];
    const float* linb       = (const float*)d_in[9];
    const float* out_gamma  = (const float*)d_in[10];
    const float* projW      = (const float*)d_in[11];
    const float* projb      = (const float*)d_in[12];
    float* out = (float*)d_out;

    float* rotM_ptr;
    cudaGetSymbolAddress((void**)&rotM_ptr, g_rotM);
    float* res_ptr;
    cudaGetSymbolAddress((void**)&res_ptr, g_res);

    const int smem_lift = 4 * 128 * SAL * (int)sizeof(__nv_bfloat16);   // 90112
    const int smem_gemm = 4 * 128 * SA * (int)sizeof(__nv_bfloat16);    // 73728 -> 3 CTAs/SM
    cudaFuncSetAttribute(lift_mma, cudaFuncAttributeMaxDynamicSharedMemorySize, smem_lift);
    cudaFuncSetAttribute(gemm_mma, cudaFuncAttributeMaxDynamicSharedMemorySize, smem_gemm);

    // Order chosen so lift_mma is the 4th launch (ncu capture target).
    feats_kernel<<<BN*32/256, 256>>>(coords, freq);
    repack_lift<<<(1024*KL + 255)/256, 256>>>(liftW);
    rotor_pre<<<4, 256>>>(rotor_th);
    lift_mma<<<dim3(8, BN/128), 256, smem_lift>>>(liftb);
    repack<<<(NL*8*CN*CN + 255)/256, 256>>>(linW);
    ln_in_kernel<<<BN/2, 256>>>(in_gamma, norm_gamma, act_alpha);

    for (int l = 0; l < NL; l++) {
        gemm_mma<<<dim3(BN/128, 8), 256, smem_gemm>>>(l);
        int fin = (l == NL-1) ? 1 : 0;
        const float* gnext = fin ? out_gamma : (norm_gamma + (size_t)(l+1)*CN*4);
        const float* anext = fin ? act_alpha : (act_alpha + (size_t)(l+1)*CN);
        const float* resIn = (l == 0) ? res_ptr : (out + AMU_SIZE + (size_t)(l-1)*SLICE);
        ip_kernel<<<BN/2, 256>>>(rotM_ptr + (size_t)(fin ? 0 : (l+1))*64*CN,
                                 linb + (size_t)l*CN*8,
                                 resIn,
                                 out + AMU_SIZE + (size_t)l*SLICE,
                                 gnext, anext,
                                 projW, projb, out, fin);
    }
}

// round 12
// speedup vs baseline: 1.2244x; 1.2244x over previous
#include <cuda_runtime.h>
#include <cuda_bf16.h>
#include <math.h>
#include <stdint.h>

#define BN 8192
#define CN 128
#define NL 8
#define BC (BN*CN)
#define SLICE (BC*8)
#define AMU_SIZE (BN*32)
#define EPSF 1e-6f
#define KL 160   // lift K padded (132 -> 160)
#define SAL 88   // lift SMEM row stride (bf16): conflict-free
#define SW 40    // gemm SMEM row stride (bf16): conflict-free

// ------------------------- device scratch -------------------------
__device__ __nv_bfloat16 g_feats_hi[BN*KL];
__device__ __nv_bfloat16 g_feats_lo[BN*KL];
__device__ __nv_bfloat16 g_LW_hi[1024*KL];      // liftW transposed [n][k]
__device__ __nv_bfloat16 g_LW_lo[1024*KL];
__device__ __nv_bfloat16 g_Wb_hi[NL*8*CN*CN];   // [l][kb][o][i]
__device__ __nv_bfloat16 g_Wb_lo[NL*8*CN*CN];
__device__ float g_rotM[NL*64*CN];              // transposed rotor matrices [l][jk][c]
__device__ float g_h[BC*8];                     // lift output interleaved
__device__ float g_res[BC*8];                   // layer-0 residual
__device__ __nv_bfloat16 g_act_hi[8*BC];        // blade-planar activations (hi)
__device__ __nv_bfloat16 g_act_lo[8*BC];        // (lo)
__device__ float g_gout[8*BC];                  // blade-planar gemm output

__device__ const int c_blades[8] = {0,1,2,4,3,5,6,7};

__device__ __forceinline__ int cl_sign(int a, int b) {
    int s = 0; int aa = a >> 1;
    while (aa) { s += __popc(aa & b); aa >>= 1; }
    return (s & 1) ? -1 : 1;
}

__device__ __forceinline__ uint32_t smem_u32(const void* p) {
    uint32_t a;
    asm("{ .reg .u64 t; cvta.to.shared.u64 t, %1; cvt.u32.u64 %0, t; }" : "=r"(a) : "l"(p));
    return a;
}

__device__ __forceinline__ void cp16(uint32_t dst, const void* src) {
    asm volatile("cp.async.cg.shared.global [%0], [%1], 16;" :: "r"(dst), "l"(src));
}

__device__ __forceinline__ void mma16816(float* c, const uint32_t* a, const uint32_t* b) {
    asm volatile("mma.sync.aligned.m16n8k16.row.col.f32.bf16.bf16.f32 "
        "{%0,%1,%2,%3}, {%4,%5,%6,%7}, {%8,%9}, {%0,%1,%2,%3};"
        : "+f"(c[0]), "+f"(c[1]), "+f"(c[2]), "+f"(c[3])
        : "r"(a[0]), "r"(a[1]), "r"(a[2]), "r"(a[3]), "r"(b[0]), "r"(b[1]));
}

// ------------------------- merged prep kernel -------------------------
// blocks [0, 4096): repack lin_W
// blocks [4096, 4736): repack lift_W
// blocks [4736, 4740): rotor_pre
// blocks [4740, 5764): feats
#define PREP_REPACK   4096
#define PREP_RLIFT    (PREP_REPACK + 640)
#define PREP_ROTOR    (PREP_RLIFT + 4)
#define PREP_TOTAL    (PREP_ROTOR + 1024)

__global__ void __launch_bounds__(256) prep_kernel(
    const float* __restrict__ linW, const float* __restrict__ liftW,
    const float* __restrict__ theta,
    const float* __restrict__ coords, const float* __restrict__ freq)
{
    int bid = blockIdx.x;
    if (bid < PREP_REPACK) {
        int n = bid * 256 + threadIdx.x;
        int i = n & 127;
        int o = (n >> 7) & 127;
        int kb = (n >> 14) & 7;
        int l = n >> 17;
        float w = linW[(size_t)(((l*128 + o)*128 + i) * 8) + kb];
        __nv_bfloat16 hi = __float2bfloat16(w);
        g_Wb_hi[n] = hi;
        g_Wb_lo[n] = __float2bfloat16(w - __bfloat162float(hi));
    } else if (bid < PREP_RLIFT) {
        int n = (bid - PREP_REPACK) * 256 + threadIdx.x;
        if (n < 1024*KL) {
            int k = n % KL;
            int o = n / KL;
            float w = (k < 132) ? liftW[(size_t)k*1024 + o] : 0.0f;
            __nv_bfloat16 hi = __float2bfloat16(w);
            g_LW_hi[n] = hi;
            g_LW_lo[n] = __float2bfloat16(w - __bfloat162float(hi));
        }
    } else if (bid < PREP_ROTOR) {
        int n = (bid - PREP_RLIFT) * 256 + threadIdx.x;
        if (n < NL * CN) {
            int l = n / CN, c = n % CN;
            const float* t = theta + n * 3;
            float ang = sqrtf(t[0]*t[0] + t[1]*t[1] + t[2]*t[2] + EPSF);
            float R[8] = {0,0,0,0,0,0,0,0};
            R[0] = cosf(ang);
            float s = sinf(ang) / ang;
            R[4] = s * t[0]; R[5] = s * t[1]; R[6] = s * t[2];
            float Rr[8];
            #pragma unroll
            for (int i = 0; i < 8; i++) Rr[i] = (i >= 4) ? -R[i] : R[i];
            float M[64];
            #pragma unroll
            for (int i = 0; i < 64; i++) M[i] = 0.0f;
            const int iv[4] = {0, 4, 5, 6};
            for (int ii = 0; ii < 4; ii++) {
                int i = iv[ii]; float Ri = R[i]; int a = c_blades[i];
                for (int j = 0; j < 8; j++) {
                    int bb = c_blades[j];
                    int m_mask = a ^ bb;
                    float tj = Ri * (float)cl_sign(a, bb);
                    for (int pp = 0; pp < 4; pp++) {
                        int p = iv[pp]; int pm = c_blades[p];
                        int k_mask = m_mask ^ pm;
                        float s2 = (float)cl_sign(m_mask, pm);
                        int k = c_blades[k_mask];
                        M[j*8 + k] += tj * Rr[p] * s2;
                    }
                }
            }
            float* out = g_rotM + (size_t)l*64*CN + c;
            #pragma unroll
            for (int i = 0; i < 64; i++) out[(size_t)i*CN] = M[i];
        }
    } else {
        int gid = (bid - PREP_ROTOR) * 256 + threadIdx.x;
        int row = gid >> 5, lane = gid & 31;
        if (row >= BN) return;
        float c0 = coords[row*4+0], c1 = coords[row*4+1];
        float c2 = coords[row*4+2], c3 = coords[row*4+3];
        __nv_bfloat16* oh = g_feats_hi + (size_t)row * KL;
        __nv_bfloat16* ol = g_feats_lo + (size_t)row * KL;
        if (lane < 4) {
            float v = coords[row*4 + lane];
            __nv_bfloat16 hi = __float2bfloat16(v);
            oh[lane] = hi; ol[lane] = __float2bfloat16(v - __bfloat162float(hi));
        }
        #pragma unroll
        for (int f = lane; f < 64; f += 32) {
            float p = c0*freq[f] + c1*freq[64+f] + c2*freq[128+f] + c3*freq[192+f];
            float sv = sinf(p), cv = cosf(p);
            __nv_bfloat16 sh = __float2bfloat16(sv);
            __nv_bfloat16 ch = __float2bfloat16(cv);
            oh[4 + f]  = sh; ol[4 + f]  = __float2bfloat16(sv - __bfloat162float(sh));
            oh[68 + f] = ch; ol[68 + f] = __float2bfloat16(cv - __bfloat162float(ch));
        }
        if (lane < 28) {
            oh[132 + lane] = __float2bfloat16(0.0f);
            ol[132 + lane] = __float2bfloat16(0.0f);
        }
    }
}

// ------------------------- lift GEMM via mma -------------------------
__global__ void __launch_bounds__(256, 2) lift_mma(const float* __restrict__ liftb) {
    extern __shared__ __nv_bfloat16 sm[];
    __nv_bfloat16* sAhi = sm;
    __nv_bfloat16* sAlo = sm + 128*SAL;
    __nv_bfloat16* sBhi = sm + 2*128*SAL;
    __nv_bfloat16* sBlo = sm + 3*128*SAL;

    int tid = threadIdx.x;
    int wid = tid >> 5, lane = tid & 31;
    int group = lane >> 2, tig = lane & 3;
    int m_warp = (wid & 3) * 32;
    int n_warp = (wid >> 2) * 64;

    int nb = blockIdx.x << 7;
    int mb = blockIdx.y << 7;

    const __nv_bfloat16* Ahi = g_feats_hi + (size_t)mb*KL;
    const __nv_bfloat16* Alo = g_feats_lo + (size_t)mb*KL;
    const __nv_bfloat16* Bhi = g_LW_hi + (size_t)nb*KL;
    const __nv_bfloat16* Blo = g_LW_lo + (size_t)nb*KL;

    float acc[2][8][4];
    #pragma unroll
    for (int f = 0; f < 2; f++)
        #pragma unroll
        for (int g = 0; g < 8; g++)
            #pragma unroll
            for (int q = 0; q < 4; q++) acc[f][g][q] = 0.0f;

    #pragma unroll
    for (int chunk = 0; chunk < 2; chunk++) {
        int kc = chunk * 80;
        #pragma unroll
        for (int i = 0; i < 5; i++) {
            int idx = tid + 256*i;
            int row = idx / 10, ch = idx % 10;
            size_t src = (size_t)row*KL + kc + ch*8;
            int dst = row*SAL + ch*8;
            *(uint4*)&sAhi[dst] = *(const uint4*)&Ahi[src];
            *(uint4*)&sAlo[dst] = *(const uint4*)&Alo[src];
            *(uint4*)&sBhi[dst] = *(const uint4*)&Bhi[src];
            *(uint4*)&sBlo[dst] = *(const uint4*)&Blo[src];
        }
        __syncthreads();

        #pragma unroll
        for (int ks = 0; ks < 5; ks++) {
            int k0 = ks * 16;
            uint32_t ahi[2][4], alo[2][4];
            #pragma unroll
            for (int f = 0; f < 2; f++) {
                int r0 = (m_warp + f*16 + group) * SAL + k0 + tig*2;
                int r8 = r0 + 8*SAL;
                ahi[f][0] = *(const uint32_t*)&sAhi[r0];
                ahi[f][1] = *(const uint32_t*)&sAhi[r8];
                ahi[f][2] = *(const uint32_t*)&sAhi[r0 + 8];
                ahi[f][3] = *(const uint32_t*)&sAhi[r8 + 8];
                alo[f][0] = *(const uint32_t*)&sAlo[r0];
                alo[f][1] = *(const uint32_t*)&sAlo[r8];
                alo[f][2] = *(const uint32_t*)&sAlo[r0 + 8];
                alo[f][3] = *(const uint32_t*)&sAlo[r8 + 8];
            }
            #pragma unroll
            for (int g = 0; g < 8; g++) {
                int nrow = (n_warp + g*8 + group) * SAL + k0 + tig*2;
                uint32_t bhi[2], blo[2];
                bhi[0] = *(const uint32_t*)&sBhi[nrow];
                bhi[1] = *(const uint32_t*)&sBhi[nrow + 8];
                blo[0] = *(const uint32_t*)&sBlo[nrow];
                blo[1] = *(const uint32_t*)&sBlo[nrow + 8];
                #pragma unroll
                for (int f = 0; f < 2; f++) {
                    mma16816(acc[f][g], ahi[f], bhi);
                    mma16816(acc[f][g], ahi[f], blo);
                    mma16816(acc[f][g], alo[f], bhi);
                }
            }
        }
        __syncthreads();
    }

    #pragma unroll
    for (int f = 0; f < 2; f++) {
        #pragma unroll
        for (int g = 0; g < 8; g++) {
            int row = mb + m_warp + f*16 + group;
            int col = nb + n_warp + g*8 + tig*2;
            float b0 = liftb[col], b1 = liftb[col+1];
            float* p = g_h + (size_t)row*1024 + col;
            *(float2*)p = make_float2(acc[f][g][0] + b0, acc[f][g][1] + b1);
            *(float2*)(p + 8*1024) = make_float2(acc[f][g][2] + b0, acc[f][g][3] + b1);
        }
    }
}

// ------------------------- persistent 2-tile blade GEMM (cp.async 2-stage) -------------------------
// grid = 256 CTAs; CTA b handles tiles (kb = b>>5, mb = (b&31)) and (kb, mb+32).
__device__ __forceinline__ void gemm_load_chunk2(
    const __nv_bfloat16* Ahi0, const __nv_bfloat16* Alo0,
    const __nv_bfloat16* Ahi1, const __nv_bfloat16* Alo1,
    const __nv_bfloat16* Bhi, const __nv_bfloat16* Blo,
    __nv_bfloat16* base, int q, int tid)
{
    const int P = 128*SW;
    const __nv_bfloat16* Ahi = (q < 4) ? Ahi0 : Ahi1;
    const __nv_bfloat16* Alo = (q < 4) ? Alo0 : Alo1;
    int kc = (q & 3) * 32;
    #pragma unroll
    for (int e = 0; e < 2; e++) {
        int id = tid + 256*e;
        int r = id >> 2, kv = id & 3;
        int ko = kc + kv*8;
        int dst = r*SW + kv*8;
        cp16(smem_u32(base + dst),         Ahi + (size_t)r*128 + ko);
        cp16(smem_u32(base + P + dst),     Alo + (size_t)r*128 + ko);
        cp16(smem_u32(base + 2*P + dst),   Bhi + (size_t)r*128 + ko);
        cp16(smem_u32(base + 3*P + dst),   Blo + (size_t)r*128 + ko);
    }
    asm volatile("cp.async.commit_group;" ::: "memory");
}

__global__ void __launch_bounds__(256, 2) gemm_mma(int l) {
    extern __shared__ __nv_bfloat16 sm[];
    const int P = 128*SW;

    int tid = threadIdx.x;
    int wid = tid >> 5, lane = tid & 31;
    int group = lane >> 2, tig = lane & 3;
    int m_warp = (wid & 3) * 32;
    int n_warp = (wid >> 2) * 64;

    int kb  = blockIdx.x >> 5;
    int mb0 = (blockIdx.x & 31) << 7;
    int mb1 = mb0 + (32 << 7);

    const __nv_bfloat16* Ahi0 = g_act_hi + (size_t)kb*BC + (size_t)mb0*128;
    const __nv_bfloat16* Alo0 = g_act_lo + (size_t)kb*BC + (size_t)mb0*128;
    const __nv_bfloat16* Ahi1 = g_act_hi + (size_t)kb*BC + (size_t)mb1*128;
    const __nv_bfloat16* Alo1 = g_act_lo + (size_t)kb*BC + (size_t)mb1*128;
    const __nv_bfloat16* Bhi = g_Wb_hi + (size_t)(l*8 + kb)*CN*CN;
    const __nv_bfloat16* Blo = g_Wb_lo + (size_t)(l*8 + kb)*CN*CN;

    float acc[2][8][4];
    #pragma unroll
    for (int f = 0; f < 2; f++)
        #pragma unroll
        for (int g = 0; g < 8; g++)
            #pragma unroll
            for (int q = 0; q < 4; q++) acc[f][g][q] = 0.0f;

    gemm_load_chunk2(Ahi0, Alo0, Ahi1, Alo1, Bhi, Blo, sm,       0, tid);
    gemm_load_chunk2(Ahi0, Alo0, Ahi1, Alo1, Bhi, Blo, sm + 4*P, 1, tid);

    #pragma unroll
    for (int q = 0; q < 8; q++) {
        if (q < 7) asm volatile("cp.async.wait_group 1;" ::: "memory");
        else       asm volatile("cp.async.wait_group 0;" ::: "memory");
        __syncthreads();

        __nv_bfloat16* base = sm + (q & 1) * 4*P;
        __nv_bfloat16* sAhi = base;
        __nv_bfloat16* sAlo = base + P;
        __nv_bfloat16* sBhi = base + 2*P;
        __nv_bfloat16* sBlo = base + 3*P;

        #pragma unroll
        for (int ks = 0; ks < 2; ks++) {
            int k0 = ks * 16;
            uint32_t ahi[2][4], alo[2][4];
            #pragma unroll
            for (int f = 0; f < 2; f++) {
                int r0 = (m_warp + f*16 + group) * SW + k0 + tig*2;
                int r8 = r0 + 8*SW;
                ahi[f][0] = *(const uint32_t*)&sAhi[r0];
                ahi[f][1] = *(const uint32_t*)&sAhi[r8];
                ahi[f][2] = *(const uint32_t*)&sAhi[r0 + 8];
                ahi[f][3] = *(const uint32_t*)&sAhi[r8 + 8];
                alo[f][0] = *(const uint32_t*)&sAlo[r0];
                alo[f][1] = *(const uint32_t*)&sAlo[r8];
                alo[f][2] = *(const uint32_t*)&sAlo[r0 + 8];
                alo[f][3] = *(const uint32_t*)&sAlo[r8 + 8];
            }
            #pragma unroll
            for (int g = 0; g < 8; g++) {
                int nrow = (n_warp + g*8 + group) * SW + k0 + tig*2;
                uint32_t bhi[2], blo[2];
                bhi[0] = *(const uint32_t*)&sBhi[nrow];
                bhi[1] = *(const uint32_t*)&sBhi[nrow + 8];
                blo[0] = *(const uint32_t*)&sBlo[nrow];
                blo[1] = *(const uint32_t*)&sBlo[nrow + 8];
                #pragma unroll
                for (int f = 0; f < 2; f++) {
                    mma16816(acc[f][g], ahi[f], bhi);
                    mma16816(acc[f][g], ahi[f], blo);
                    mma16816(acc[f][g], alo[f], bhi);
                }
            }
        }
        __syncthreads();
        if (q < 6) gemm_load_chunk2(Ahi0, Alo0, Ahi1, Alo1, Bhi, Blo, sm + (q & 1)*4*P, q + 2, tid);

        // end of a tile: store + reset accumulators
        if (q == 3 || q == 7) {
            int mb = (q == 3) ? mb0 : mb1;
            float* gbase = g_gout + (size_t)kb*BC;
            #pragma unroll
            for (int f = 0; f < 2; f++) {
                #pragma unroll
                for (int g = 0; g < 8; g++) {
                    int row = mb + m_warp + f*16 + group;
                    int col = n_warp + g*8 + tig*2;
                    float* p = gbase + (size_t)row*128 + col;
                    *(float2*)p = make_float2(acc[f][g][0], acc[f][g][1]);
                    *(float2*)(p + 8*128) = make_float2(acc[f][g][2], acc[f][g][3]);
                    if (q == 3) {
                        acc[f][g][0] = 0.0f; acc[f][g][1] = 0.0f;
                        acc[f][g][2] = 0.0f; acc[f][g][3] = 0.0f;
                    }
                }
            }
        }
    }
}

// ------------------------- pointwise helpers -------------------------
__device__ __forceinline__ void grade_inv(const float* x, float* inv, float (*sred)[4], int c) {
    float v[4];
    v[0] = x[0]*x[0];
    v[1] = x[1]*x[1] + x[2]*x[2] + x[3]*x[3];
    v[2] = x[4]*x[4] + x[5]*x[5] + x[6]*x[6];
    v[3] = x[7]*x[7];
    #pragma unroll
    for (int g = 0; g < 4; g++) {
        float t = v[g];
        t += __shfl_xor_sync(0xffffffffu, t, 16);
        t += __shfl_xor_sync(0xffffffffu, t, 8);
        t += __shfl_xor_sync(0xffffffffu, t, 4);
        t += __shfl_xor_sync(0xffffffffu, t, 2);
        t += __shfl_xor_sync(0xffffffffu, t, 1);
        if ((c & 31) == 0) sred[g][c >> 5] = t;
    }
    __syncthreads();
    #pragma unroll
    for (int g = 0; g < 4; g++)
        inv[g] = rsqrtf((sred[g][0]+sred[g][1]+sred[g][2]+sred[g][3]) * (1.0f/128.0f) + EPSF);
    __syncthreads();
}

__device__ __forceinline__ void ln_apply(float* x, const float* gamma, const float* inv, int c) {
    float f0 = gamma[c*4+0] * inv[0];
    float f1 = gamma[c*4+1] * inv[1];
    float f2 = gamma[c*4+2] * inv[2];
    float f3 = gamma[c*4+3] * inv[3];
    x[0] *= f0;
    x[1] *= f1; x[2] *= f1; x[3] *= f1;
    x[4] *= f2; x[5] *= f2; x[6] *= f2;
    x[7] *= f3;
}

__device__ __forceinline__ void rot_gelu_store(const float* x, const float* __restrict__ Mt,
                                               float alpha, int b, int c) {
    float y[8] = {0,0,0,0,0,0,0,0};
    #pragma unroll
    for (int j = 0; j < 8; j++) {
        float xj = x[j];
        #pragma unroll
        for (int k = 0; k < 8; k++)
            y[k] = fmaf(xj, __ldg(Mt + (size_t)(j*8+k)*CN + c), y[k]);
    }
    float nn = EPSF;
    #pragma unroll
    for (int k = 0; k < 8; k++) nn = fmaf(y[k], y[k], nn);
    float gate = 0.5f * (1.0f + erff(alpha * sqrtf(nn) * 0.70710678118654752f));
    #pragma unroll
    for (int k = 0; k < 8; k++) {
        float v = y[k] * gate;
        __nv_bfloat16 hi = __float2bfloat16(v);
        size_t idx = (size_t)k*BC + b*128 + c;
        g_act_hi[idx] = hi;
        g_act_lo[idx] = __float2bfloat16(v - __bfloat162float(hi));
    }
}

// ------------------------- input norm + layer-0 prologue -------------------------
__global__ void __launch_bounds__(256) ln_in_kernel(const float* __restrict__ in_gamma,
                                                    const float* __restrict__ ng0,
                                                    const float* __restrict__ alpha0) {
    __shared__ float sred[2][4][4];
    int row = threadIdx.x >> 7;
    int c = threadIdx.x & 127;
    int b = blockIdx.x * 2 + row;
    float x[8];
    const float* p = g_h + (size_t)(b*128 + c) * 8;
    *(float4*)x     = *(const float4*)p;
    *(float4*)(x+4) = *(const float4*)(p+4);

    float inv[4];
    grade_inv(x, inv, sred[row], c);
    ln_apply(x, in_gamma, inv, c);

    float* pr = g_res + (size_t)(b*128 + c) * 8;
    *(float4*)pr     = *(const float4*)x;
    *(float4*)(pr+4) = *(const float4*)(x+4);

    grade_inv(x, inv, sred[row], c);
    ln_apply(x, ng0, inv, c);
    rot_gelu_store(x, g_rotM, alpha0[c], b, c);
}

// ------------------------- inter-layer pointwise (final layer fuses projection) ------------
__global__ void __launch_bounds__(256) ip_kernel(const float* __restrict__ Mt_next,
                                                 const float* __restrict__ linb,
                                                 const float* __restrict__ resIn,
                                                 float* __restrict__ outI,
                                                 const float* __restrict__ gamma_next,
                                                 const float* __restrict__ alpha_next,
                                                 const float* __restrict__ projW,
                                                 const float* __restrict__ projb,
                                                 float* __restrict__ outA,
                                                 int final_ln) {
    __shared__ float sred[2][4][4];
    __shared__ float sproj[8][12];
    int row = threadIdx.x >> 7;
    int c = threadIdx.x & 127;
    int b = blockIdx.x * 2 + row;
    float x[8];
    #pragma unroll
    for (int k = 0; k < 8; k++)
        x[k] = g_gout[(size_t)k*BC + b*128 + c] + linb[c*8 + k];

    const float* pr = resIn + (size_t)(b*128 + c) * 8;
    float r[8];
    *(float4*)r     = *(const float4*)pr;
    *(float4*)(r+4) = *(const float4*)(pr+4);
    #pragma unroll
    for (int k = 0; k < 8; k++) x[k] += r[k];

    float* po = outI + (size_t)(b*128 + c) * 8;
    *(float4*)po     = *(const float4*)x;
    *(float4*)(po+4) = *(const float4*)(x+4);

    float inv[4];
    grade_inv(x, inv, sred[row], c);
    ln_apply(x, gamma_next, inv, c);

    if (!final_ln) {
        rot_gelu_store(x, Mt_next, alpha_next[c], b, c);
    } else {
        float p[12];
        #pragma unroll
        for (int o = 0; o < 4; o++)
            #pragma unroll
            for (int kk = 0; kk < 3; kk++)
                p[o*3+kk] = x[4+kk] * __ldg(projW + (size_t)(o*128 + c)*8 + 4 + kk);
        #pragma unroll
        for (int q = 0; q < 12; q++) {
            float t = p[q];
            t += __shfl_xor_sync(0xffffffffu, t, 16);
            t += __shfl_xor_sync(0xffffffffu, t, 8);
            t += __shfl_xor_sync(0xffffffffu, t, 4);
            t += __shfl_xor_sync(0xffffffffu, t, 2);
            t += __shfl_xor_sync(0xffffffffu, t, 1);
            p[q] = t;
        }
        int wp = threadIdx.x >> 5;
        if ((threadIdx.x & 31) == 0) {
            #pragma unroll
            for (int q = 0; q < 12; q++) sproj[wp][q] = p[q];
        }
        __syncthreads();
        int tid = threadIdx.x;
        if (tid < 64) {
            int rr = tid >> 5, j = tid & 31;
            int k = j & 7;
            int bb = blockIdx.x * 2 + rr;
            if (k < 4 || k > 6) outA[(size_t)bb*32 + j] = 0.0f;
        }
        if (tid < 24) {
            int rr = tid / 12, q = tid % 12;
            int o = q / 3, k = 4 + q % 3;
            int bb = blockIdx.x * 2 + rr;
            float s = sproj[rr*4+0][q] + sproj[rr*4+1][q] + sproj[rr*4+2][q] + sproj[rr*4+3][q];
            outA[(size_t)bb*32 + o*8 + k] = s + projb[o*8 + k];
        }
    }
}

// ------------------------- launch -------------------------
extern "C" void kernel_launch(void* const* d_in, const int* in_sizes, int n_in,
                              void* d_out, int out_size) {
    const float* coords     = (const float*)d_in[0];
    const float* freq       = (const float*)d_in[1];
    const float* liftW      = (const float*)d_in[2];
    const float* liftb      = (const float*)d_in[3];
    const float* in_gamma   = (const float*)d_in[4];
    const float* norm_gamma = (const float*)d_in[5];
    const float* rotor_th   = (const float*)d_in[6];
    const float* act_alpha  = (const float*)d_in[7];
    const float* linW       = (const float*)d_in[8];
    const float* linb       = (const float*)d_in[9];
    const float* out_gamma  = (const float*)d_in[10];
    const float* projW      = (const float*)d_in[11];
    const float* projb      = (const float*)d_in[12];
    float* out = (float*)d_out;

    float* rotM_ptr;
    cudaGetSymbolAddress((void**)&rotM_ptr, g_rotM);
    float* res_ptr;
    cudaGetSymbolAddress((void**)&res_ptr, g_res);

    const int smem_lift = 4 * 128 * SAL * (int)sizeof(__nv_bfloat16);   // 90112
    const int smem_gemm = 2 * 4 * 128 * SW * (int)sizeof(__nv_bfloat16); // 81920
    cudaFuncSetAttribute(lift_mma, cudaFuncAttributeMaxDynamicSharedMemorySize, smem_lift);
    cudaFuncSetAttribute(gemm_mma, cudaFuncAttributeMaxDynamicSharedMemorySize, smem_gemm);

    // Launch order: prep(1), lift(2), ln_in(3), gemm(4) -> ncu captures gemm_mma.
    prep_kernel<<<PREP_TOTAL, 256>>>(linW, liftW, rotor_th, coords, freq);
    lift_mma<<<dim3(8, BN/128), 256, smem_lift>>>(liftb);
    ln_in_kernel<<<BN/2, 256>>>(in_gamma, norm_gamma, act_alpha);

    for (int l = 0; l < NL; l++) {
        gemm_mma<<<256, 256, smem_gemm>>>(l);
        int fin = (l == NL-1) ? 1 : 0;
        const float* gnext = fin ? out_gamma : (norm_gamma + (size_t)(l+1)*CN*4);
        const float* anext = fin ? act_alpha : (act_alpha + (size_t)(l+1)*CN);
        const float* resIn = (l == 0) ? res_ptr : (out + AMU_SIZE + (size_t)(l-1)*SLICE);
        ip_kernel<<<BN/2, 256>>>(rotM_ptr + (size_t)(fin ? 0 : (l+1))*64*CN,
                                 linb + (size_t)l*CN*8,
                                 resIn,
                                 out + AMU_SIZE + (size_t)l*SLICE,
                                 gnext, anext,
                                 projW, projb, out, fin);
    }
}

// round 13
// speedup vs baseline: 1.2430x; 1.0152x over previous
#include <cuda_runtime.h>
#include <cuda_bf16.h>
#include <math.h>
#include <stdint.h>

#define BN 8192
#define CN 128
#define NL 8
#define BC (BN*CN)
#define SLICE (BC*8)
#define AMU_SIZE (BN*32)
#define EPSF 1e-6f
#define KL 160   // lift K padded (132 -> 160)
#define SAL 88   // lift SMEM row stride (bf16): conflict-free
#define SW 40    // gemm SMEM row stride (bf16): conflict-free

// ------------------------- device scratch -------------------------
__device__ __nv_bfloat16 g_feats_hi[BN*KL];
__device__ __nv_bfloat16 g_feats_lo[BN*KL];
__device__ __nv_bfloat16 g_LW_hi[1024*KL];      // liftW transposed [n][k]
__device__ __nv_bfloat16 g_LW_lo[1024*KL];
__device__ __nv_bfloat16 g_Wb_hi[NL*8*CN*CN];   // [l][kb][o][i]
__device__ __nv_bfloat16 g_Wb_lo[NL*8*CN*CN];
__device__ float g_rotM[NL*64*CN];              // transposed rotor matrices [l][jk][c]
__device__ float g_h[BC*8];                     // lift output interleaved
__device__ float g_res[BC*8];                   // layer-0 residual
__device__ __nv_bfloat16 g_act_hi[8*BC];        // blade-planar activations (hi)
__device__ __nv_bfloat16 g_act_lo[8*BC];        // (lo)
__device__ float g_gout[8*BC];                  // blade-planar gemm output

__device__ const int c_blades[8] = {0,1,2,4,3,5,6,7};

__device__ __forceinline__ int cl_sign(int a, int b) {
    int s = 0; int aa = a >> 1;
    while (aa) { s += __popc(aa & b); aa >>= 1; }
    return (s & 1) ? -1 : 1;
}

__device__ __forceinline__ uint32_t smem_u32(const void* p) {
    uint32_t a;
    asm("{ .reg .u64 t; cvta.to.shared.u64 t, %1; cvt.u32.u64 %0, t; }" : "=r"(a) : "l"(p));
    return a;
}

__device__ __forceinline__ void cp16(uint32_t dst, const void* src) {
    asm volatile("cp.async.cg.shared.global [%0], [%1], 16;" :: "r"(dst), "l"(src));
}

__device__ __forceinline__ void mma16816(float* c, const uint32_t* a, const uint32_t* b) {
    asm volatile("mma.sync.aligned.m16n8k16.row.col.f32.bf16.bf16.f32 "
        "{%0,%1,%2,%3}, {%4,%5,%6,%7}, {%8,%9}, {%0,%1,%2,%3};"
        : "+f"(c[0]), "+f"(c[1]), "+f"(c[2]), "+f"(c[3])
        : "r"(a[0]), "r"(a[1]), "r"(a[2]), "r"(a[3]), "r"(b[0]), "r"(b[1]));
}

// ------------------------- merged prep kernel -------------------------
#define PREP_REPACK   4096
#define PREP_RLIFT    (PREP_REPACK + 640)
#define PREP_ROTOR    (PREP_RLIFT + 4)
#define PREP_TOTAL    (PREP_ROTOR + 1024)

__global__ void __launch_bounds__(256) prep_kernel(
    const float* __restrict__ linW, const float* __restrict__ liftW,
    const float* __restrict__ theta,
    const float* __restrict__ coords, const float* __restrict__ freq)
{
    int bid = blockIdx.x;
    if (bid < PREP_REPACK) {
        int n = bid * 256 + threadIdx.x;
        int i = n & 127;
        int o = (n >> 7) & 127;
        int kb = (n >> 14) & 7;
        int l = n >> 17;
        float w = linW[(size_t)(((l*128 + o)*128 + i) * 8) + kb];
        __nv_bfloat16 hi = __float2bfloat16(w);
        g_Wb_hi[n] = hi;
        g_Wb_lo[n] = __float2bfloat16(w - __bfloat162float(hi));
    } else if (bid < PREP_RLIFT) {
        int n = (bid - PREP_REPACK) * 256 + threadIdx.x;
        if (n < 1024*KL) {
            int k = n % KL;
            int o = n / KL;
            float w = (k < 132) ? liftW[(size_t)k*1024 + o] : 0.0f;
            __nv_bfloat16 hi = __float2bfloat16(w);
            g_LW_hi[n] = hi;
            g_LW_lo[n] = __float2bfloat16(w - __bfloat162float(hi));
        }
    } else if (bid < PREP_ROTOR) {
        int n = (bid - PREP_RLIFT) * 256 + threadIdx.x;
        if (n < NL * CN) {
            int l = n / CN, c = n % CN;
            const float* t = theta + n * 3;
            float ang = sqrtf(t[0]*t[0] + t[1]*t[1] + t[2]*t[2] + EPSF);
            float R[8] = {0,0,0,0,0,0,0,0};
            R[0] = cosf(ang);
            float s = sinf(ang) / ang;
            R[4] = s * t[0]; R[5] = s * t[1]; R[6] = s * t[2];
            float Rr[8];
            #pragma unroll
            for (int i = 0; i < 8; i++) Rr[i] = (i >= 4) ? -R[i] : R[i];
            float M[64];
            #pragma unroll
            for (int i = 0; i < 64; i++) M[i] = 0.0f;
            const int iv[4] = {0, 4, 5, 6};
            for (int ii = 0; ii < 4; ii++) {
                int i = iv[ii]; float Ri = R[i]; int a = c_blades[i];
                for (int j = 0; j < 8; j++) {
                    int bb = c_blades[j];
                    int m_mask = a ^ bb;
                    float tj = Ri * (float)cl_sign(a, bb);
                    for (int pp = 0; pp < 4; pp++) {
                        int p = iv[pp]; int pm = c_blades[p];
                        int k_mask = m_mask ^ pm;
                        float s2 = (float)cl_sign(m_mask, pm);
                        int k = c_blades[k_mask];
                        M[j*8 + k] += tj * Rr[p] * s2;
                    }
                }
            }
            float* out = g_rotM + (size_t)l*64*CN + c;
            #pragma unroll
            for (int i = 0; i < 64; i++) out[(size_t)i*CN] = M[i];
        }
    } else {
        int gid = (bid - PREP_ROTOR) * 256 + threadIdx.x;
        int row = gid >> 5, lane = gid & 31;
        if (row >= BN) return;
        float c0 = coords[row*4+0], c1 = coords[row*4+1];
        float c2 = coords[row*4+2], c3 = coords[row*4+3];
        __nv_bfloat16* oh = g_feats_hi + (size_t)row * KL;
        __nv_bfloat16* ol = g_feats_lo + (size_t)row * KL;
        if (lane < 4) {
            float v = coords[row*4 + lane];
            __nv_bfloat16 hi = __float2bfloat16(v);
            oh[lane] = hi; ol[lane] = __float2bfloat16(v - __bfloat162float(hi));
        }
        #pragma unroll
        for (int f = lane; f < 64; f += 32) {
            float p = c0*freq[f] + c1*freq[64+f] + c2*freq[128+f] + c3*freq[192+f];
            float sv = sinf(p), cv = cosf(p);
            __nv_bfloat16 sh = __float2bfloat16(sv);
            __nv_bfloat16 ch = __float2bfloat16(cv);
            oh[4 + f]  = sh; ol[4 + f]  = __float2bfloat16(sv - __bfloat162float(sh));
            oh[68 + f] = ch; ol[68 + f] = __float2bfloat16(cv - __bfloat162float(ch));
        }
        if (lane < 28) {
            oh[132 + lane] = __float2bfloat16(0.0f);
            ol[132 + lane] = __float2bfloat16(0.0f);
        }
    }
}

// ------------------------- lift GEMM via mma -------------------------
__global__ void __launch_bounds__(256, 2) lift_mma(const float* __restrict__ liftb) {
    extern __shared__ __nv_bfloat16 sm[];
    __nv_bfloat16* sAhi = sm;
    __nv_bfloat16* sAlo = sm + 128*SAL;
    __nv_bfloat16* sBhi = sm + 2*128*SAL;
    __nv_bfloat16* sBlo = sm + 3*128*SAL;

    int tid = threadIdx.x;
    int wid = tid >> 5, lane = tid & 31;
    int group = lane >> 2, tig = lane & 3;
    int m_warp = (wid & 3) * 32;
    int n_warp = (wid >> 2) * 64;

    int nb = blockIdx.x << 7;
    int mb = blockIdx.y << 7;

    const __nv_bfloat16* Ahi = g_feats_hi + (size_t)mb*KL;
    const __nv_bfloat16* Alo = g_feats_lo + (size_t)mb*KL;
    const __nv_bfloat16* Bhi = g_LW_hi + (size_t)nb*KL;
    const __nv_bfloat16* Blo = g_LW_lo + (size_t)nb*KL;

    float acc[2][8][4];
    #pragma unroll
    for (int f = 0; f < 2; f++)
        #pragma unroll
        for (int g = 0; g < 8; g++)
            #pragma unroll
            for (int q = 0; q < 4; q++) acc[f][g][q] = 0.0f;

    #pragma unroll
    for (int chunk = 0; chunk < 2; chunk++) {
        int kc = chunk * 80;
        #pragma unroll
        for (int i = 0; i < 5; i++) {
            int idx = tid + 256*i;
            int row = idx / 10, ch = idx % 10;
            size_t src = (size_t)row*KL + kc + ch*8;
            int dst = row*SAL + ch*8;
            *(uint4*)&sAhi[dst] = *(const uint4*)&Ahi[src];
            *(uint4*)&sAlo[dst] = *(const uint4*)&Alo[src];
            *(uint4*)&sBhi[dst] = *(const uint4*)&Bhi[src];
            *(uint4*)&sBlo[dst] = *(const uint4*)&Blo[src];
        }
        __syncthreads();

        #pragma unroll
        for (int ks = 0; ks < 5; ks++) {
            int k0 = ks * 16;
            uint32_t ahi[2][4], alo[2][4];
            #pragma unroll
            for (int f = 0; f < 2; f++) {
                int r0 = (m_warp + f*16 + group) * SAL + k0 + tig*2;
                int r8 = r0 + 8*SAL;
                ahi[f][0] = *(const uint32_t*)&sAhi[r0];
                ahi[f][1] = *(const uint32_t*)&sAhi[r8];
                ahi[f][2] = *(const uint32_t*)&sAhi[r0 + 8];
                ahi[f][3] = *(const uint32_t*)&sAhi[r8 + 8];
                alo[f][0] = *(const uint32_t*)&sAlo[r0];
                alo[f][1] = *(const uint32_t*)&sAlo[r8];
                alo[f][2] = *(const uint32_t*)&sAlo[r0 + 8];
                alo[f][3] = *(const uint32_t*)&sAlo[r8 + 8];
            }
            #pragma unroll
            for (int g = 0; g < 8; g++) {
                int nrow = (n_warp + g*8 + group) * SAL + k0 + tig*2;
                uint32_t bhi[2], blo[2];
                bhi[0] = *(const uint32_t*)&sBhi[nrow];
                bhi[1] = *(const uint32_t*)&sBhi[nrow + 8];
                blo[0] = *(const uint32_t*)&sBlo[nrow];
                blo[1] = *(const uint32_t*)&sBlo[nrow + 8];
                #pragma unroll
                for (int f = 0; f < 2; f++) {
                    mma16816(acc[f][g], ahi[f], bhi);
                    mma16816(acc[f][g], ahi[f], blo);
                    mma16816(acc[f][g], alo[f], bhi);
                }
            }
        }
        __syncthreads();
    }

    #pragma unroll
    for (int f = 0; f < 2; f++) {
        #pragma unroll
        for (int g = 0; g < 8; g++) {
            int row = mb + m_warp + f*16 + group;
            int col = nb + n_warp + g*8 + tig*2;
            float b0 = liftb[col], b1 = liftb[col+1];
            float* p = g_h + (size_t)row*1024 + col;
            *(float2*)p = make_float2(acc[f][g][0] + b0, acc[f][g][1] + b1);
            *(float2*)(p + 8*1024) = make_float2(acc[f][g][2] + b0, acc[f][g][3] + b1);
        }
    }
}

// ------------------------- N-split blade GEMM: tile 128m x 64n, 3 CTAs/SM -------------------------
// grid (64, 16): x = m-tile, y = kb*2 + n-half. Warp tile 32x32, acc = 32 regs.
#define PA (128*SW)
#define PB (64*SW)
#define STG (2*PA + 2*PB)

__device__ __forceinline__ void gemm_load_chunk_ns(
    const __nv_bfloat16* Ahi, const __nv_bfloat16* Alo,
    const __nv_bfloat16* Bhi, const __nv_bfloat16* Blo,
    __nv_bfloat16* base, int kc, int tid)
{
    // A: 128 rows x 32 k = 512 uint4 per plane
    #pragma unroll
    for (int e = 0; e < 2; e++) {
        int id = tid + 256*e;
        int r = id >> 2, kv = id & 3;
        int ko = kc + kv*8;
        int dst = r*SW + kv*8;
        cp16(smem_u32(base + dst),      Ahi + (size_t)r*128 + ko);
        cp16(smem_u32(base + PA + dst), Alo + (size_t)r*128 + ko);
    }
    // B: 64 rows x 32 k = 256 uint4 per plane
    {
        int r = tid >> 2, kv = tid & 3;
        int ko = kc + kv*8;
        int dst = r*SW + kv*8;
        cp16(smem_u32(base + 2*PA + dst),      Bhi + (size_t)r*128 + ko);
        cp16(smem_u32(base + 2*PA + PB + dst), Blo + (size_t)r*128 + ko);
    }
    asm volatile("cp.async.commit_group;" ::: "memory");
}

__global__ void __launch_bounds__(256, 3) gemm_mma(int l) {
    extern __shared__ __nv_bfloat16 sm[];

    int tid = threadIdx.x;
    int wid = tid >> 5, lane = tid & 31;
    int group = lane >> 2, tig = lane & 3;
    int mw = (wid & 3) * 32;
    int nw = (wid >> 2) * 32;

    int mb = blockIdx.x << 7;
    int kb = blockIdx.y >> 1;
    int nh = (blockIdx.y & 1) * 64;

    const __nv_bfloat16* Ahi = g_act_hi + (size_t)kb*BC + (size_t)mb*128;
    const __nv_bfloat16* Alo = g_act_lo + (size_t)kb*BC + (size_t)mb*128;
    const __nv_bfloat16* Bhi = g_Wb_hi + (size_t)(l*8 + kb)*CN*CN + (size_t)nh*128;
    const __nv_bfloat16* Blo = g_Wb_lo + (size_t)(l*8 + kb)*CN*CN + (size_t)nh*128;

    float acc[2][4][4];
    #pragma unroll
    for (int f = 0; f < 2; f++)
        #pragma unroll
        for (int g = 0; g < 4; g++)
            #pragma unroll
            for (int q = 0; q < 4; q++) acc[f][g][q] = 0.0f;

    gemm_load_chunk_ns(Ahi, Alo, Bhi, Blo, sm,       0,  tid);
    gemm_load_chunk_ns(Ahi, Alo, Bhi, Blo, sm + STG, 32, tid);

    #pragma unroll
    for (int c = 0; c < 4; c++) {
        if (c < 3) asm volatile("cp.async.wait_group 1;" ::: "memory");
        else       asm volatile("cp.async.wait_group 0;" ::: "memory");
        __syncthreads();

        __nv_bfloat16* base = sm + (c & 1) * STG;
        __nv_bfloat16* sAhi = base;
        __nv_bfloat16* sAlo = base + PA;
        __nv_bfloat16* sBhi = base + 2*PA;
        __nv_bfloat16* sBlo = base + 2*PA + PB;

        #pragma unroll
        for (int ks = 0; ks < 2; ks++) {
            int k0 = ks * 16;
            uint32_t ahi[2][4], alo[2][4];
            #pragma unroll
            for (int f = 0; f < 2; f++) {
                int r0 = (mw + f*16 + group) * SW + k0 + tig*2;
                int r8 = r0 + 8*SW;
                ahi[f][0] = *(const uint32_t*)&sAhi[r0];
                ahi[f][1] = *(const uint32_t*)&sAhi[r8];
                ahi[f][2] = *(const uint32_t*)&sAhi[r0 + 8];
                ahi[f][3] = *(const uint32_t*)&sAhi[r8 + 8];
                alo[f][0] = *(const uint32_t*)&sAlo[r0];
                alo[f][1] = *(const uint32_t*)&sAlo[r8];
                alo[f][2] = *(const uint32_t*)&sAlo[r0 + 8];
                alo[f][3] = *(const uint32_t*)&sAlo[r8 + 8];
            }
            #pragma unroll
            for (int g = 0; g < 4; g++) {
                int nrow = (nw + g*8 + group) * SW + k0 + tig*2;
                uint32_t bhi[2], blo[2];
                bhi[0] = *(const uint32_t*)&sBhi[nrow];
                bhi[1] = *(const uint32_t*)&sBhi[nrow + 8];
                blo[0] = *(const uint32_t*)&sBlo[nrow];
                blo[1] = *(const uint32_t*)&sBlo[nrow + 8];
                #pragma unroll
                for (int f = 0; f < 2; f++) {
                    mma16816(acc[f][g], ahi[f], bhi);
                    mma16816(acc[f][g], ahi[f], blo);
                    mma16816(acc[f][g], alo[f], bhi);
                }
            }
        }
        __syncthreads();
        if (c < 2) gemm_load_chunk_ns(Ahi, Alo, Bhi, Blo, sm + (c & 1)*STG, (c + 2)*32, tid);
    }

    float* gbase = g_gout + (size_t)kb*BC;
    #pragma unroll
    for (int f = 0; f < 2; f++) {
        #pragma unroll
        for (int g = 0; g < 4; g++) {
            int row = mb + mw + f*16 + group;
            int col = nh + nw + g*8 + tig*2;
            float* p = gbase + (size_t)row*128 + col;
            *(float2*)p = make_float2(acc[f][g][0], acc[f][g][1]);
            *(float2*)(p + 8*128) = make_float2(acc[f][g][2], acc[f][g][3]);
        }
    }
}

// ------------------------- pointwise helpers -------------------------
__device__ __forceinline__ void grade_inv(const float* x, float* inv, float (*sred)[4], int c) {
    float v[4];
    v[0] = x[0]*x[0];
    v[1] = x[1]*x[1] + x[2]*x[2] + x[3]*x[3];
    v[2] = x[4]*x[4] + x[5]*x[5] + x[6]*x[6];
    v[3] = x[7]*x[7];
    #pragma unroll
    for (int g = 0; g < 4; g++) {
        float t = v[g];
        t += __shfl_xor_sync(0xffffffffu, t, 16);
        t += __shfl_xor_sync(0xffffffffu, t, 8);
        t += __shfl_xor_sync(0xffffffffu, t, 4);
        t += __shfl_xor_sync(0xffffffffu, t, 2);
        t += __shfl_xor_sync(0xffffffffu, t, 1);
        if ((c & 31) == 0) sred[g][c >> 5] = t;
    }
    __syncthreads();
    #pragma unroll
    for (int g = 0; g < 4; g++)
        inv[g] = rsqrtf((sred[g][0]+sred[g][1]+sred[g][2]+sred[g][3]) * (1.0f/128.0f) + EPSF);
    __syncthreads();
}

__device__ __forceinline__ void ln_apply(float* x, const float* gamma, const float* inv, int c) {
    float f0 = gamma[c*4+0] * inv[0];
    float f1 = gamma[c*4+1] * inv[1];
    float f2 = gamma[c*4+2] * inv[2];
    float f3 = gamma[c*4+3] * inv[3];
    x[0] *= f0;
    x[1] *= f1; x[2] *= f1; x[3] *= f1;
    x[4] *= f2; x[5] *= f2; x[6] *= f2;
    x[7] *= f3;
}

__device__ __forceinline__ void rot_gelu_store(const float* x, const float* __restrict__ Mt,
                                               float alpha, int b, int c) {
    float y[8] = {0,0,0,0,0,0,0,0};
    #pragma unroll
    for (int j = 0; j < 8; j++) {
        float xj = x[j];
        #pragma unroll
        for (int k = 0; k < 8; k++)
            y[k] = fmaf(xj, __ldg(Mt + (size_t)(j*8+k)*CN + c), y[k]);
    }
    float nn = EPSF;
    #pragma unroll
    for (int k = 0; k < 8; k++) nn = fmaf(y[k], y[k], nn);
    float gate = 0.5f * (1.0f + erff(alpha * sqrtf(nn) * 0.70710678118654752f));
    #pragma unroll
    for (int k = 0; k < 8; k++) {
        float v = y[k] * gate;
        __nv_bfloat16 hi = __float2bfloat16(v);
        size_t idx = (size_t)k*BC + b*128 + c;
        g_act_hi[idx] = hi;
        g_act_lo[idx] = __float2bfloat16(v - __bfloat162float(hi));
    }
}

// ------------------------- input norm + layer-0 prologue -------------------------
__global__ void __launch_bounds__(256) ln_in_kernel(const float* __restrict__ in_gamma,
                                                    const float* __restrict__ ng0,
                                                    const float* __restrict__ alpha0) {
    __shared__ float sred[2][4][4];
    int row = threadIdx.x >> 7;
    int c = threadIdx.x & 127;
    int b = blockIdx.x * 2 + row;
    float x[8];
    const float* p = g_h + (size_t)(b*128 + c) * 8;
    *(float4*)x     = *(const float4*)p;
    *(float4*)(x+4) = *(const float4*)(p+4);

    float inv[4];
    grade_inv(x, inv, sred[row], c);
    ln_apply(x, in_gamma, inv, c);

    float* pr = g_res + (size_t)(b*128 + c) * 8;
    *(float4*)pr     = *(const float4*)x;
    *(float4*)(pr+4) = *(const float4*)(x+4);

    grade_inv(x, inv, sred[row], c);
    ln_apply(x, ng0, inv, c);
    rot_gelu_store(x, g_rotM, alpha0[c], b, c);
}

// ------------------------- inter-layer pointwise (final layer fuses projection) ------------
__global__ void __launch_bounds__(256) ip_kernel(const float* __restrict__ Mt_next,
                                                 const float* __restrict__ linb,
                                                 const float* __restrict__ resIn,
                                                 float* __restrict__ outI,
                                                 const float* __restrict__ gamma_next,
                                                 const float* __restrict__ alpha_next,
                                                 const float* __restrict__ projW,
                                                 const float* __restrict__ projb,
                                                 float* __restrict__ outA,
                                                 int final_ln) {
    __shared__ float sred[2][4][4];
    __shared__ float sproj[8][12];
    int row = threadIdx.x >> 7;
    int c = threadIdx.x & 127;
    int b = blockIdx.x * 2 + row;
    float x[8];
    #pragma unroll
    for (int k = 0; k < 8; k++)
        x[k] = g_gout[(size_t)k*BC + b*128 + c] + linb[c*8 + k];

    const float* pr = resIn + (size_t)(b*128 + c) * 8;
    float r[8];
    *(float4*)r     = *(const float4*)pr;
    *(float4*)(r+4) = *(const float4*)(pr+4);
    #pragma unroll
    for (int k = 0; k < 8; k++) x[k] += r[k];

    float* po = outI + (size_t)(b*128 + c) * 8;
    *(float4*)po     = *(const float4*)x;
    *(float4*)(po+4) = *(const float4*)(x+4);

    float inv[4];
    grade_inv(x, inv, sred[row], c);
    ln_apply(x, gamma_next, inv, c);

    if (!final_ln) {
        rot_gelu_store(x, Mt_next, alpha_next[c], b, c);
    } else {
        float p[12];
        #pragma unroll
        for (int o = 0; o < 4; o++)
            #pragma unroll
            for (int kk = 0; kk < 3; kk++)
                p[o*3+kk] = x[4+kk] * __ldg(projW + (size_t)(o*128 + c)*8 + 4 + kk);
        #pragma unroll
        for (int q = 0; q < 12; q++) {
            float t = p[q];
            t += __shfl_xor_sync(0xffffffffu, t, 16);
            t += __shfl_xor_sync(0xffffffffu, t, 8);
            t += __shfl_xor_sync(0xffffffffu, t, 4);
            t += __shfl_xor_sync(0xffffffffu, t, 2);
            t += __shfl_xor_sync(0xffffffffu, t, 1);
            p[q] = t;
        }
        int wp = threadIdx.x >> 5;
        if ((threadIdx.x & 31) == 0) {
            #pragma unroll
            for (int q = 0; q < 12; q++) sproj[wp][q] = p[q];
        }
        __syncthreads();
        int tid = threadIdx.x;
        if (tid < 64) {
            int rr = tid >> 5, j = tid & 31;
            int k = j & 7;
            int bb = blockIdx.x * 2 + rr;
            if (k < 4 || k > 6) outA[(size_t)bb*32 + j] = 0.0f;
        }
        if (tid < 24) {
            int rr = tid / 12, q = tid % 12;
            int o = q / 3, k = 4 + q % 3;
            int bb = blockIdx.x * 2 + rr;
            float s = sproj[rr*4+0][q] + sproj[rr*4+1][q] + sproj[rr*4+2][q] + sproj[rr*4+3][q];
            outA[(size_t)bb*32 + o*8 + k] = s + projb[o*8 + k];
        }
    }
}

// ------------------------- launch -------------------------
extern "C" void kernel_launch(void* const* d_in, const int* in_sizes, int n_in,
                              void* d_out, int out_size) {
    const float* coords     = (const float*)d_in[0];
    const float* freq       = (const float*)d_in[1];
    const float* liftW      = (const float*)d_in[2];
    const float* liftb      = (const float*)d_in[3];
    const float* in_gamma   = (const float*)d_in[4];
    const float* norm_gamma = (const float*)d_in[5];
    const float* rotor_th   = (const float*)d_in[6];
    const float* act_alpha  = (const float*)d_in[7];
    const float* linW       = (const float*)d_in[8];
    const float* linb       = (const float*)d_in[9];
    const float* out_gamma  = (const float*)d_in[10];
    const float* projW      = (const float*)d_in[11];
    const float* projb      = (const float*)d_in[12];
    float* out = (float*)d_out;

    float* rotM_ptr;
    cudaGetSymbolAddress((void**)&rotM_ptr, g_rotM);
    float* res_ptr;
    cudaGetSymbolAddress((void**)&res_ptr, g_res);

    const int smem_lift = 4 * 128 * SAL * (int)sizeof(__nv_bfloat16);   // 90112
    const int smem_gemm = 2 * STG * (int)sizeof(__nv_bfloat16);         // 61440
    cudaFuncSetAttribute(lift_mma, cudaFuncAttributeMaxDynamicSharedMemorySize, smem_lift);
    cudaFuncSetAttribute(gemm_mma, cudaFuncAttributeMaxDynamicSharedMemorySize, smem_gemm);

    // Launch order: prep(1), lift(2), ln_in(3), gemm(4) -> ncu captures gemm_mma.
    prep_kernel<<<PREP_TOTAL, 256>>>(linW, liftW, rotor_th, coords, freq);
    lift_mma<<<dim3(8, BN/128), 256, smem_lift>>>(liftb);
    ln_in_kernel<<<BN/2, 256>>>(in_gamma, norm_gamma, act_alpha);

    for (int l = 0; l < NL; l++) {
        gemm_mma<<<dim3(64, 16), 256, smem_gemm>>>(l);
        int fin = (l == NL-1) ? 1 : 0;
        const float* gnext = fin ? out_gamma : (norm_gamma + (size_t)(l+1)*CN*4);
        const float* anext = fin ? act_alpha : (act_alpha + (size_t)(l+1)*CN);
        const float* resIn = (l == 0) ? res_ptr : (out + AMU_SIZE + (size_t)(l-1)*SLICE);
        ip_kernel<<<BN/2, 256>>>(rotM_ptr + (size_t)(fin ? 0 : (l+1))*64*CN,
                                 linb + (size_t)l*CN*8,
                                 resIn,
                                 out + AMU_SIZE + (size_t)l*SLICE,
                                 gnext, anext,
                                 projW, projb, out, fin);
    }
}

// round 14
// speedup vs baseline: 1.2708x; 1.0224x over previous
#include <cuda_runtime.h>
#include <cuda_bf16.h>
#include <math.h>
#include <stdint.h>

#define BN 8192
#define CN 128
#define NL 8
#define BC (BN*CN)
#define SLICE (BC*8)
#define AMU_SIZE (BN*32)
#define EPSF 1e-6f
#define KL 160   // lift K padded
#define SAL 88   // lift SMEM row stride (bf16)
#define SW 40    // A-chunk SMEM row stride (bf16): 20 words -> conflict-free
#define SB 136   // resident-B SMEM row stride (bf16): 68 words == 4 mod 32 -> conflict-free

// ------------------------- device scratch -------------------------
__device__ __nv_bfloat16 g_feats_hi[BN*KL];
__device__ __nv_bfloat16 g_feats_lo[BN*KL];
__device__ __nv_bfloat16 g_LW_hi[1024*KL];
__device__ __nv_bfloat16 g_LW_lo[1024*KL];
__device__ __nv_bfloat16 g_Wb_hi[NL*8*CN*CN];   // [l][kb][o][i]
__device__ __nv_bfloat16 g_Wb_lo[NL*8*CN*CN];
__device__ float g_rotM[NL*64*CN];
__device__ float g_h[BC*8];
__device__ float g_res[BC*8];
__device__ __nv_bfloat16 g_act_hi[8*BC];
__device__ __nv_bfloat16 g_act_lo[8*BC];
__device__ float g_gout[8*BC];

__device__ const int c_blades[8] = {0,1,2,4,3,5,6,7};

__device__ __forceinline__ int cl_sign(int a, int b) {
    int s = 0; int aa = a >> 1;
    while (aa) { s += __popc(aa & b); aa >>= 1; }
    return (s & 1) ? -1 : 1;
}

__device__ __forceinline__ uint32_t smem_u32(const void* p) {
    uint32_t a;
    asm("{ .reg .u64 t; cvta.to.shared.u64 t, %1; cvt.u32.u64 %0, t; }" : "=r"(a) : "l"(p));
    return a;
}

__device__ __forceinline__ void cp16(uint32_t dst, const void* src) {
    asm volatile("cp.async.cg.shared.global [%0], [%1], 16;" :: "r"(dst), "l"(src));
}

__device__ __forceinline__ void mma16816(float* c, const uint32_t* a, const uint32_t* b) {
    asm volatile("mma.sync.aligned.m16n8k16.row.col.f32.bf16.bf16.f32 "
        "{%0,%1,%2,%3}, {%4,%5,%6,%7}, {%8,%9}, {%0,%1,%2,%3};"
        : "+f"(c[0]), "+f"(c[1]), "+f"(c[2]), "+f"(c[3])
        : "r"(a[0]), "r"(a[1]), "r"(a[2]), "r"(a[3]), "r"(b[0]), "r"(b[1]));
}

// ------------------------- merged prep kernel -------------------------
#define PREP_REPACK   4096
#define PREP_RLIFT    (PREP_REPACK + 640)
#define PREP_ROTOR    (PREP_RLIFT + 4)
#define PREP_TOTAL    (PREP_ROTOR + 1024)

__global__ void __launch_bounds__(256) prep_kernel(
    const float* __restrict__ linW, const float* __restrict__ liftW,
    const float* __restrict__ theta,
    const float* __restrict__ coords, const float* __restrict__ freq)
{
    int bid = blockIdx.x;
    if (bid < PREP_REPACK) {
        int n = bid * 256 + threadIdx.x;
        int i = n & 127;
        int o = (n >> 7) & 127;
        int kb = (n >> 14) & 7;
        int l = n >> 17;
        float w = linW[(size_t)(((l*128 + o)*128 + i) * 8) + kb];
        __nv_bfloat16 hi = __float2bfloat16(w);
        g_Wb_hi[n] = hi;
        g_Wb_lo[n] = __float2bfloat16(w - __bfloat162float(hi));
    } else if (bid < PREP_RLIFT) {
        int n = (bid - PREP_REPACK) * 256 + threadIdx.x;
        if (n < 1024*KL) {
            int k = n % KL;
            int o = n / KL;
            float w = (k < 132) ? liftW[(size_t)k*1024 + o] : 0.0f;
            __nv_bfloat16 hi = __float2bfloat16(w);
            g_LW_hi[n] = hi;
            g_LW_lo[n] = __float2bfloat16(w - __bfloat162float(hi));
        }
    } else if (bid < PREP_ROTOR) {
        int n = (bid - PREP_RLIFT) * 256 + threadIdx.x;
        if (n < NL * CN) {
            int l = n / CN, c = n % CN;
            const float* t = theta + n * 3;
            float ang = sqrtf(t[0]*t[0] + t[1]*t[1] + t[2]*t[2] + EPSF);
            float R[8] = {0,0,0,0,0,0,0,0};
            R[0] = cosf(ang);
            float s = sinf(ang) / ang;
            R[4] = s * t[0]; R[5] = s * t[1]; R[6] = s * t[2];
            float Rr[8];
            #pragma unroll
            for (int i = 0; i < 8; i++) Rr[i] = (i >= 4) ? -R[i] : R[i];
            float M[64];
            #pragma unroll
            for (int i = 0; i < 64; i++) M[i] = 0.0f;
            const int iv[4] = {0, 4, 5, 6};
            for (int ii = 0; ii < 4; ii++) {
                int i = iv[ii]; float Ri = R[i]; int a = c_blades[i];
                for (int j = 0; j < 8; j++) {
                    int bb = c_blades[j];
                    int m_mask = a ^ bb;
                    float tj = Ri * (float)cl_sign(a, bb);
                    for (int pp = 0; pp < 4; pp++) {
                        int p = iv[pp]; int pm = c_blades[p];
                        int k_mask = m_mask ^ pm;
                        float s2 = (float)cl_sign(m_mask, pm);
                        int k = c_blades[k_mask];
                        M[j*8 + k] += tj * Rr[p] * s2;
                    }
                }
            }
            float* out = g_rotM + (size_t)l*64*CN + c;
            #pragma unroll
            for (int i = 0; i < 64; i++) out[(size_t)i*CN] = M[i];
        }
    } else {
        int gid = (bid - PREP_ROTOR) * 256 + threadIdx.x;
        int row = gid >> 5, lane = gid & 31;
        if (row >= BN) return;
        float c0 = coords[row*4+0], c1 = coords[row*4+1];
        float c2 = coords[row*4+2], c3 = coords[row*4+3];
        __nv_bfloat16* oh = g_feats_hi + (size_t)row * KL;
        __nv_bfloat16* ol = g_feats_lo + (size_t)row * KL;
        if (lane < 4) {
            float v = coords[row*4 + lane];
            __nv_bfloat16 hi = __float2bfloat16(v);
            oh[lane] = hi; ol[lane] = __float2bfloat16(v - __bfloat162float(hi));
        }
        #pragma unroll
        for (int f = lane; f < 64; f += 32) {
            float p = c0*freq[f] + c1*freq[64+f] + c2*freq[128+f] + c3*freq[192+f];
            float sv = sinf(p), cv = cosf(p);
            __nv_bfloat16 sh = __float2bfloat16(sv);
            __nv_bfloat16 ch = __float2bfloat16(cv);
            oh[4 + f]  = sh; ol[4 + f]  = __float2bfloat16(sv - __bfloat162float(sh));
            oh[68 + f] = ch; ol[68 + f] = __float2bfloat16(cv - __bfloat162float(ch));
        }
        if (lane < 28) {
            oh[132 + lane] = __float2bfloat16(0.0f);
            ol[132 + lane] = __float2bfloat16(0.0f);
        }
    }
}

// ------------------------- lift GEMM via mma -------------------------
__global__ void __launch_bounds__(256, 2) lift_mma(const float* __restrict__ liftb) {
    extern __shared__ __nv_bfloat16 sm[];
    __nv_bfloat16* sAhi = sm;
    __nv_bfloat16* sAlo = sm + 128*SAL;
    __nv_bfloat16* sBhi = sm + 2*128*SAL;
    __nv_bfloat16* sBlo = sm + 3*128*SAL;

    int tid = threadIdx.x;
    int wid = tid >> 5, lane = tid & 31;
    int group = lane >> 2, tig = lane & 3;
    int m_warp = (wid & 3) * 32;
    int n_warp = (wid >> 2) * 64;

    int nb = blockIdx.x << 7;
    int mb = blockIdx.y << 7;

    const __nv_bfloat16* Ahi = g_feats_hi + (size_t)mb*KL;
    const __nv_bfloat16* Alo = g_feats_lo + (size_t)mb*KL;
    const __nv_bfloat16* Bhi = g_LW_hi + (size_t)nb*KL;
    const __nv_bfloat16* Blo = g_LW_lo + (size_t)nb*KL;

    float acc[2][8][4];
    #pragma unroll
    for (int f = 0; f < 2; f++)
        #pragma unroll
        for (int g = 0; g < 8; g++)
            #pragma unroll
            for (int q = 0; q < 4; q++) acc[f][g][q] = 0.0f;

    #pragma unroll
    for (int chunk = 0; chunk < 2; chunk++) {
        int kc = chunk * 80;
        #pragma unroll
        for (int i = 0; i < 5; i++) {
            int idx = tid + 256*i;
            int row = idx / 10, ch = idx % 10;
            size_t src = (size_t)row*KL + kc + ch*8;
            int dst = row*SAL + ch*8;
            *(uint4*)&sAhi[dst] = *(const uint4*)&Ahi[src];
            *(uint4*)&sAlo[dst] = *(const uint4*)&Alo[src];
            *(uint4*)&sBhi[dst] = *(const uint4*)&Bhi[src];
            *(uint4*)&sBlo[dst] = *(const uint4*)&Blo[src];
        }
        __syncthreads();

        #pragma unroll
        for (int ks = 0; ks < 5; ks++) {
            int k0 = ks * 16;
            uint32_t ahi[2][4], alo[2][4];
            #pragma unroll
            for (int f = 0; f < 2; f++) {
                int r0 = (m_warp + f*16 + group) * SAL + k0 + tig*2;
                int r8 = r0 + 8*SAL;
                ahi[f][0] = *(const uint32_t*)&sAhi[r0];
                ahi[f][1] = *(const uint32_t*)&sAhi[r8];
                ahi[f][2] = *(const uint32_t*)&sAhi[r0 + 8];
                ahi[f][3] = *(const uint32_t*)&sAhi[r8 + 8];
                alo[f][0] = *(const uint32_t*)&sAlo[r0];
                alo[f][1] = *(const uint32_t*)&sAlo[r8];
                alo[f][2] = *(const uint32_t*)&sAlo[r0 + 8];
                alo[f][3] = *(const uint32_t*)&sAlo[r8 + 8];
            }
            #pragma unroll
            for (int g = 0; g < 8; g++) {
                int nrow = (n_warp + g*8 + group) * SAL + k0 + tig*2;
                uint32_t bhi[2], blo[2];
                bhi[0] = *(const uint32_t*)&sBhi[nrow];
                bhi[1] = *(const uint32_t*)&sBhi[nrow + 8];
                blo[0] = *(const uint32_t*)&sBlo[nrow];
                blo[1] = *(const uint32_t*)&sBlo[nrow + 8];
                #pragma unroll
                for (int f = 0; f < 2; f++) {
                    mma16816(acc[f][g], ahi[f], bhi);
                    mma16816(acc[f][g], ahi[f], blo);
                    mma16816(acc[f][g], alo[f], bhi);
                }
            }
        }
        __syncthreads();
    }

    #pragma unroll
    for (int f = 0; f < 2; f++) {
        #pragma unroll
        for (int g = 0; g < 8; g++) {
            int row = mb + m_warp + f*16 + group;
            int col = nb + n_warp + g*8 + tig*2;
            float b0 = liftb[col], b1 = liftb[col+1];
            float* p = g_h + (size_t)row*1024 + col;
            *(float2*)p = make_float2(acc[f][g][0] + b0, acc[f][g][1] + b1);
            *(float2*)(p + 8*1024) = make_float2(acc[f][g][2] + b0, acc[f][g][3] + b1);
        }
    }
}

// ------------------------- B-resident persistent blade GEMM -------------------------
// grid (32, 8): x = m-group (2 tiles of 128 rows), y = blade.
// SMEM: B hi/lo resident (full K), A streamed in 32-k chunks, 2-stage.
#define PBF (128*SB)          // one B plane (bf16 units)
#define PAC (128*SW)          // one A plane per chunk
#define ABASE (2*PBF)         // A stages start
#define ASTG (2*PAC)          // per stage: Ahi + Alo

__device__ __forceinline__ void loadA_chunk(
    const __nv_bfloat16* Ahi, const __nv_bfloat16* Alo,
    __nv_bfloat16* sm, int stage, int kc, int tid)
{
    __nv_bfloat16* base = sm + ABASE + stage*ASTG;
    #pragma unroll
    for (int e = 0; e < 2; e++) {
        int id = tid + 256*e;
        int r = id >> 2, kv = id & 3;
        int ko = kc + kv*8;
        int dst = r*SW + kv*8;
        cp16(smem_u32(base + dst),       Ahi + (size_t)r*128 + ko);
        cp16(smem_u32(base + PAC + dst), Alo + (size_t)r*128 + ko);
    }
    asm volatile("cp.async.commit_group;" ::: "memory");
}

__global__ void __launch_bounds__(256, 2) gemm_mma(int l) {
    extern __shared__ __nv_bfloat16 sm[];
    __nv_bfloat16* sBhi = sm;
    __nv_bfloat16* sBlo = sm + PBF;

    int tid = threadIdx.x;
    int wid = tid >> 5, lane = tid & 31;
    int group = lane >> 2, tig = lane & 3;
    int m_warp = (wid & 3) * 32;
    int n_warp = (wid >> 2) * 64;

    int mg = blockIdx.x;          // m-group: rows [mg*256, mg*256+256)
    int kb = blockIdx.y;

    const __nv_bfloat16* Whi = g_Wb_hi + (size_t)(l*8 + kb)*CN*CN;
    const __nv_bfloat16* Wlo = g_Wb_lo + (size_t)(l*8 + kb)*CN*CN;
    const __nv_bfloat16* Ahi = g_act_hi + (size_t)kb*BC + (size_t)(mg*256)*128;
    const __nv_bfloat16* Alo = g_act_lo + (size_t)kb*BC + (size_t)(mg*256)*128;

    // B load (async): 2048 16B chunks per plane
    #pragma unroll
    for (int e = 0; e < 8; e++) {
        int id = tid + 256*e;          // 0..2047
        int o = id >> 4, ch = id & 15;
        size_t src = (size_t)o*128 + ch*8;
        int dst = o*SB + ch*8;
        cp16(smem_u32(sBhi + dst), Whi + src);
        cp16(smem_u32(sBlo + dst), Wlo + src);
    }
    asm volatile("cp.async.commit_group;" ::: "memory");

    loadA_chunk(Ahi, Alo, sm, 0, 0,  tid);   // tile0 chunk0
    loadA_chunk(Ahi, Alo, sm, 1, 32, tid);   // tile0 chunk1

    float acc[2][8][4];
    #pragma unroll
    for (int f = 0; f < 2; f++)
        #pragma unroll
        for (int g = 0; g < 8; g++)
            #pragma unroll
            for (int q = 0; q < 4; q++) acc[f][g][q] = 0.0f;

    #pragma unroll
    for (int q = 0; q < 8; q++) {            // tile = q>>2, chunk = q&3
        if (q < 7) asm volatile("cp.async.wait_group 1;" ::: "memory");
        else       asm volatile("cp.async.wait_group 0;" ::: "memory");
        __syncthreads();

        __nv_bfloat16* sAhi = sm + ABASE + (q & 1)*ASTG;
        __nv_bfloat16* sAlo = sAhi + PAC;
        int kc = (q & 3) * 32;

        #pragma unroll
        for (int ks = 0; ks < 2; ks++) {
            int k0 = ks * 16;
            uint32_t ahi[2][4], alo[2][4];
            #pragma unroll
            for (int f = 0; f < 2; f++) {
                int r0 = (m_warp + f*16 + group) * SW + k0 + tig*2;
                int r8 = r0 + 8*SW;
                ahi[f][0] = *(const uint32_t*)&sAhi[r0];
                ahi[f][1] = *(const uint32_t*)&sAhi[r8];
                ahi[f][2] = *(const uint32_t*)&sAhi[r0 + 8];
                ahi[f][3] = *(const uint32_t*)&sAhi[r8 + 8];
                alo[f][0] = *(const uint32_t*)&sAlo[r0];
                alo[f][1] = *(const uint32_t*)&sAlo[r8];
                alo[f][2] = *(const uint32_t*)&sAlo[r0 + 8];
                alo[f][3] = *(const uint32_t*)&sAlo[r8 + 8];
            }
            int kcol = kc + k0 + tig*2;
            #pragma unroll
            for (int g = 0; g < 8; g++) {
                int nrow = (n_warp + g*8 + group) * SB + kcol;
                uint32_t bhi[2], blo[2];
                bhi[0] = *(const uint32_t*)&sBhi[nrow];
                bhi[1] = *(const uint32_t*)&sBhi[nrow + 8];
                blo[0] = *(const uint32_t*)&sBlo[nrow];
                blo[1] = *(const uint32_t*)&sBlo[nrow + 8];
                #pragma unroll
                for (int f = 0; f < 2; f++) {
                    mma16816(acc[f][g], ahi[f], bhi);
                    mma16816(acc[f][g], ahi[f], blo);
                    mma16816(acc[f][g], alo[f], bhi);
                }
            }
        }
        __syncthreads();
        if (q < 6) {
            int qn = q + 2;
            loadA_chunk(Ahi + (qn >> 2) * (size_t)128*128,
                        Alo + (qn >> 2) * (size_t)128*128,
                        sm, q & 1, (qn & 3) * 32, tid);
        }

        if (q == 3 || q == 7) {
            int mb = mg*256 + (q >> 2)*128;
            float* gbase = g_gout + (size_t)kb*BC;
            #pragma unroll
            for (int f = 0; f < 2; f++) {
                #pragma unroll
                for (int g = 0; g < 8; g++) {
                    int row = mb + m_warp + f*16 + group;
                    int col = n_warp + g*8 + tig*2;
                    float* p = gbase + (size_t)row*128 + col;
                    *(float2*)p = make_float2(acc[f][g][0], acc[f][g][1]);
                    *(float2*)(p + 8*128) = make_float2(acc[f][g][2], acc[f][g][3]);
                    if (q == 3) {
                        acc[f][g][0] = 0.0f; acc[f][g][1] = 0.0f;
                        acc[f][g][2] = 0.0f; acc[f][g][3] = 0.0f;
                    }
                }
            }
        }
    }
}

// ------------------------- pointwise helpers -------------------------
__device__ __forceinline__ void grade_inv(const float* x, float* inv, float (*sred)[4], int c) {
    float v[4];
    v[0] = x[0]*x[0];
    v[1] = x[1]*x[1] + x[2]*x[2] + x[3]*x[3];
    v[2] = x[4]*x[4] + x[5]*x[5] + x[6]*x[6];
    v[3] = x[7]*x[7];
    #pragma unroll
    for (int g = 0; g < 4; g++) {
        float t = v[g];
        t += __shfl_xor_sync(0xffffffffu, t, 16);
        t += __shfl_xor_sync(0xffffffffu, t, 8);
        t += __shfl_xor_sync(0xffffffffu, t, 4);
        t += __shfl_xor_sync(0xffffffffu, t, 2);
        t += __shfl_xor_sync(0xffffffffu, t, 1);
        if ((c & 31) == 0) sred[g][c >> 5] = t;
    }
    __syncthreads();
    #pragma unroll
    for (int g = 0; g < 4; g++)
        inv[g] = rsqrtf((sred[g][0]+sred[g][1]+sred[g][2]+sred[g][3]) * (1.0f/128.0f) + EPSF);
    __syncthreads();
}

__device__ __forceinline__ void ln_apply(float* x, const float* gamma, const float* inv, int c) {
    float f0 = gamma[c*4+0] * inv[0];
    float f1 = gamma[c*4+1] * inv[1];
    float f2 = gamma[c*4+2] * inv[2];
    float f3 = gamma[c*4+3] * inv[3];
    x[0] *= f0;
    x[1] *= f1; x[2] *= f1; x[3] *= f1;
    x[4] *= f2; x[5] *= f2; x[6] *= f2;
    x[7] *= f3;
}

__device__ __forceinline__ void rot_gelu_store(const float* x, const float* __restrict__ Mt,
                                               float alpha, int b, int c) {
    float y[8] = {0,0,0,0,0,0,0,0};
    #pragma unroll
    for (int j = 0; j < 8; j++) {
        float xj = x[j];
        #pragma unroll
        for (int k = 0; k < 8; k++)
            y[k] = fmaf(xj, __ldg(Mt + (size_t)(j*8+k)*CN + c), y[k]);
    }
    float nn = EPSF;
    #pragma unroll
    for (int k = 0; k < 8; k++) nn = fmaf(y[k], y[k], nn);
    float gate = 0.5f * (1.0f + erff(alpha * sqrtf(nn) * 0.70710678118654752f));
    #pragma unroll
    for (int k = 0; k < 8; k++) {
        float v = y[k] * gate;
        __nv_bfloat16 hi = __float2bfloat16(v);
        size_t idx = (size_t)k*BC + b*128 + c;
        g_act_hi[idx] = hi;
        g_act_lo[idx] = __float2bfloat16(v - __bfloat162float(hi));
    }
}

// ------------------------- input norm + layer-0 prologue -------------------------
__global__ void __launch_bounds__(256) ln_in_kernel(const float* __restrict__ in_gamma,
                                                    const float* __restrict__ ng0,
                                                    const float* __restrict__ alpha0) {
    __shared__ float sred[2][4][4];
    int row = threadIdx.x >> 7;
    int c = threadIdx.x & 127;
    int b = blockIdx.x * 2 + row;
    float x[8];
    const float* p = g_h + (size_t)(b*128 + c) * 8;
    *(float4*)x     = *(const float4*)p;
    *(float4*)(x+4) = *(const float4*)(p+4);

    float inv[4];
    grade_inv(x, inv, sred[row], c);
    ln_apply(x, in_gamma, inv, c);

    float* pr = g_res + (size_t)(b*128 + c) * 8;
    *(float4*)pr     = *(const float4*)x;
    *(float4*)(pr+4) = *(const float4*)(x+4);

    grade_inv(x, inv, sred[row], c);
    ln_apply(x, ng0, inv, c);
    rot_gelu_store(x, g_rotM, alpha0[c], b, c);
}

// ------------------------- inter-layer pointwise (final layer fuses projection) ------------
__global__ void __launch_bounds__(256) ip_kernel(const float* __restrict__ Mt_next,
                                                 const float* __restrict__ linb,
                                                 const float* __restrict__ resIn,
                                                 float* __restrict__ outI,
                                                 const float* __restrict__ gamma_next,
                                                 const float* __restrict__ alpha_next,
                                                 const float* __restrict__ projW,
                                                 const float* __restrict__ projb,
                                                 float* __restrict__ outA,
                                                 int final_ln) {
    __shared__ float sred[2][4][4];
    __shared__ float sproj[8][12];
    int row = threadIdx.x >> 7;
    int c = threadIdx.x & 127;
    int b = blockIdx.x * 2 + row;
    float x[8];
    #pragma unroll
    for (int k = 0; k < 8; k++)
        x[k] = g_gout[(size_t)k*BC + b*128 + c] + linb[c*8 + k];

    const float* pr = resIn + (size_t)(b*128 + c) * 8;
    float r[8];
    *(float4*)r     = *(const float4*)pr;
    *(float4*)(r+4) = *(const float4*)(pr+4);
    #pragma unroll
    for (int k = 0; k < 8; k++) x[k] += r[k];

    float* po = outI + (size_t)(b*128 + c) * 8;
    *(float4*)po     = *(const float4*)x;
    *(float4*)(po+4) = *(const float4*)(x+4);

    float inv[4];
    grade_inv(x, inv, sred[row], c);
    ln_apply(x, gamma_next, inv, c);

    if (!final_ln) {
        rot_gelu_store(x, Mt_next, alpha_next[c], b, c);
    } else {
        float p[12];
        #pragma unroll
        for (int o = 0; o < 4; o++)
            #pragma unroll
            for (int kk = 0; kk < 3; kk++)
                p[o*3+kk] = x[4+kk] * __ldg(projW + (size_t)(o*128 + c)*8 + 4 + kk);
        #pragma unroll
        for (int q = 0; q < 12; q++) {
            float t = p[q];
            t += __shfl_xor_sync(0xffffffffu, t, 16);
            t += __shfl_xor_sync(0xffffffffu, t, 8);
            t += __shfl_xor_sync(0xffffffffu, t, 4);
            t += __shfl_xor_sync(0xffffffffu, t, 2);
            t += __shfl_xor_sync(0xffffffffu, t, 1);
            p[q] = t;
        }
        int wp = threadIdx.x >> 5;
        if ((threadIdx.x & 31) == 0) {
            #pragma unroll
            for (int q = 0; q < 12; q++) sproj[wp][q] = p[q];
        }
        __syncthreads();
        int tid = threadIdx.x;
        if (tid < 64) {
            int rr = tid >> 5, j = tid & 31;
            int k = j & 7;
            int bb = blockIdx.x * 2 + rr;
            if (k < 4 || k > 6) outA[(size_t)bb*32 + j] = 0.0f;
        }
        if (tid < 24) {
            int rr = tid / 12, q = tid % 12;
            int o = q / 3, k = 4 + q % 3;
            int bb = blockIdx.x * 2 + rr;
            float s = sproj[rr*4+0][q] + sproj[rr*4+1][q] + sproj[rr*4+2][q] + sproj[rr*4+3][q];
            outA[(size_t)bb*32 + o*8 + k] = s + projb[o*8 + k];
        }
    }
}

// ------------------------- launch -------------------------
extern "C" void kernel_launch(void* const* d_in, const int* in_sizes, int n_in,
                              void* d_out, int out_size) {
    const float* coords     = (const float*)d_in[0];
    const float* freq       = (const float*)d_in[1];
    const float* liftW      = (const float*)d_in[2];
    const float* liftb      = (const float*)d_in[3];
    const float* in_gamma   = (const float*)d_in[4];
    const float* norm_gamma = (const float*)d_in[5];
    const float* rotor_th   = (const float*)d_in[6];
    const float* act_alpha  = (const float*)d_in[7];
    const float* linW       = (const float*)d_in[8];
    const float* linb       = (const float*)d_in[9];
    const float* out_gamma  = (const float*)d_in[10];
    const float* projW      = (const float*)d_in[11];
    const float* projb      = (const float*)d_in[12];
    float* out = (float*)d_out;

    float* rotM_ptr;
    cudaGetSymbolAddress((void**)&rotM_ptr, g_rotM);
    float* res_ptr;
    cudaGetSymbolAddress((void**)&res_ptr, g_res);

    const int smem_lift = 4 * 128 * SAL * (int)sizeof(__nv_bfloat16);            // 90112
    const int smem_gemm = (2*PBF + 2*ASTG) * (int)sizeof(__nv_bfloat16);         // 110592
    cudaFuncSetAttribute(lift_mma, cudaFuncAttributeMaxDynamicSharedMemorySize, smem_lift);
    cudaFuncSetAttribute(gemm_mma, cudaFuncAttributeMaxDynamicSharedMemorySize, smem_gemm);

    // Launch order: prep(1), lift(2), ln_in(3), gemm(4) -> ncu captures gemm_mma.
    prep_kernel<<<PREP_TOTAL, 256>>>(linW, liftW, rotor_th, coords, freq);
    lift_mma<<<dim3(8, BN/128), 256, smem_lift>>>(liftb);
    ln_in_kernel<<<BN/2, 256>>>(in_gamma, norm_gamma, act_alpha);

    for (int l = 0; l < NL; l++) {
        gemm_mma<<<dim3(32, 8), 256, smem_gemm>>>(l);
        int fin = (l == NL-1) ? 1 : 0;
        const float* gnext = fin ? out_gamma : (norm_gamma + (size_t)(l+1)*CN*4);
        const float* anext = fin ? act_alpha : (act_alpha + (size_t)(l+1)*CN);
        const float* resIn = (l == 0) ? res_ptr : (out + AMU_SIZE + (size_t)(l-1)*SLICE);
        ip_kernel<<<BN/2, 256>>>(rotM_ptr + (size_t)(fin ? 0 : (l+1))*64*CN,
                                 linb + (size_t)l*CN*8,
                                 resIn,
                                 out + AMU_SIZE + (size_t)l*SLICE,
                                 gnext, anext,
                                 projW, projb, out, fin);
    }
}